// round 1
// baseline (speedup 1.0000x reference)
#include <cuda_runtime.h>
#include <math.h>

// ---------------- problem constants ----------------
#define DIM   768
#define HEADS 16
#define DH    48
#define EMB   1024
#define T_    3
#define RES   24
#define HW    (RES*RES)        // 576
#define THW   (T_*HW)          // 1728
#define MLP   (4*DIM)          // 3072
#define NF    (3*DIM + MLP)    // 5376
#define KT    3
#define KH    5
#define KW    5
#define NK    (KT*KH*KW)       // 75
#define EPS   1e-5f

// ---------------- scratch (static device allocs) ----------------
__device__ float g_mod  [T_ * 2 * DIM];       // (3,1536)
__device__ float g_h    [THW * DIM];          // LN+modulated input
__device__ float g_fused[THW * NF];           // big GEMM output (mlp part pre-SiLU'd)
__device__ float g_q    [HEADS * THW * DH];
__device__ float g_k    [HEADS * THW * DH];
__device__ float g_v    [HEADS * THW * DH];
__device__ float g_xa   [THW * DIM];          // attention output (token, head*48+d)
__device__ float g_attn [THW * DIM];          // xa @ W_out
__device__ float g_mlp  [THW * DIM];          // silu(mlp_h) @ W_mlp + b

// ---------------- K1: mod = silu(emb) @ w_mod + b_mod  (3 x 1536) ----------------
__global__ void mod_kernel(const float* __restrict__ emb,
                           const float* __restrict__ w_mod,
                           const float* __restrict__ b_mod) {
    int t = blockIdx.x / 6;                         // 6 blocks of 256 per t
    int n = (blockIdx.x % 6) * 256 + threadIdx.x;   // 0..1535
    __shared__ float se[EMB];
    for (int i = threadIdx.x; i < EMB; i += 256) {
        float e = emb[t * EMB + i];
        se[i] = e / (1.f + __expf(-e));
    }
    __syncthreads();
    float acc = b_mod[n];
    for (int e = 0; e < EMB; e++)
        acc += se[e] * w_mod[e * (2 * DIM) + n];
    g_mod[t * (2 * DIM) + n] = acc;
}

// ---------------- K2: per-token LN + modulate ----------------
__global__ void ln_mod_kernel(const float* __restrict__ x) {
    int token = blockIdx.x;          // t*576 + hw
    int t  = token / HW;
    int hw = token % HW;
    int tid = threadIdx.x;           // 256
    __shared__ float red[256];

    float v[3];
    float sum = 0.f;
    #pragma unroll
    for (int i = 0; i < 3; i++) {
        int d = tid + i * 256;
        v[i] = x[((t * DIM) + d) * HW + hw];
        sum += v[i];
    }
    red[tid] = sum; __syncthreads();
    for (int s = 128; s > 0; s >>= 1) { if (tid < s) red[tid] += red[tid + s]; __syncthreads(); }
    float mean = red[0] * (1.f / DIM);
    __syncthreads();

    float sq = 0.f;
    #pragma unroll
    for (int i = 0; i < 3; i++) { float d = v[i] - mean; sq += d * d; }
    red[tid] = sq; __syncthreads();
    for (int s = 128; s > 0; s >>= 1) { if (tid < s) red[tid] += red[tid + s]; __syncthreads(); }
    float var = red[0] * (1.f / DIM);
    float rstd = rsqrtf(var + EPS);

    #pragma unroll
    for (int i = 0; i < 3; i++) {
        int d = tid + i * 256;
        float y = (v[i] - mean) * rstd;
        float scale = g_mod[t * (2 * DIM) + d];
        float shift = g_mod[t * (2 * DIM) + DIM + d];
        g_h[token * DIM + d] = y * (1.f + scale) + shift;
    }
}

// ---------------- generic fp32 SGEMM 128x128x8, bias + tail-SiLU epilogue ----------------
// C[M,N] = A[M,K](lda) @ B[K,N](row major) (+bias) (+silu on cols >= silu_from)
// Requires N % 128 == 0, K % 8 == 0; M guarded.
template<int USE_BIAS, int USE_SILU>
__global__ void __launch_bounds__(256, 2)
sgemm(const float* __restrict__ A, int lda,
      const float* __restrict__ B,
      const float* __restrict__ bias,
      float* __restrict__ C, int ldc,
      int M, int N, int K, int silu_from)
{
    __shared__ float As[8][128];
    __shared__ float Bs[8][128];
    const int tid = threadIdx.x;
    const int tx = tid & 15, ty = tid >> 4;
    const int arow = tid >> 1, acol = (tid & 1) * 4;
    const int brow = tid >> 5, bcol = (tid & 31) * 4;
    const int m0 = blockIdx.y * 128, n0 = blockIdx.x * 128;

    float acc[8][8];
    #pragma unroll
    for (int i = 0; i < 8; i++)
        #pragma unroll
        for (int j = 0; j < 8; j++) acc[i][j] = 0.f;

    const int arow_g = m0 + arow;
    const float* Ap = A + (long long)arow_g * lda + acol;
    const float* Bp = B + (long long)brow * N + n0 + bcol;

    for (int k0 = 0; k0 < K; k0 += 8) {
        float4 av = make_float4(0.f, 0.f, 0.f, 0.f);
        if (arow_g < M) av = *(const float4*)(Ap + k0);
        As[acol + 0][arow] = av.x;
        As[acol + 1][arow] = av.y;
        As[acol + 2][arow] = av.z;
        As[acol + 3][arow] = av.w;
        *(float4*)(&Bs[brow][bcol]) = *(const float4*)(Bp + (long long)k0 * N);
        __syncthreads();
        #pragma unroll
        for (int kk = 0; kk < 8; kk++) {
            float4 a0 = *(const float4*)&As[kk][ty * 8];
            float4 a1 = *(const float4*)&As[kk][ty * 8 + 4];
            float4 b0 = *(const float4*)&Bs[kk][tx * 8];
            float4 b1 = *(const float4*)&Bs[kk][tx * 8 + 4];
            float a[8] = {a0.x,a0.y,a0.z,a0.w,a1.x,a1.y,a1.z,a1.w};
            float b[8] = {b0.x,b0.y,b0.z,b0.w,b1.x,b1.y,b1.z,b1.w};
            #pragma unroll
            for (int i = 0; i < 8; i++)
                #pragma unroll
                for (int j = 0; j < 8; j++)
                    acc[i][j] = fmaf(a[i], b[j], acc[i][j]);
        }
        __syncthreads();
    }

    #pragma unroll
    for (int i = 0; i < 8; i++) {
        int row = m0 + ty * 8 + i;
        if (row >= M) continue;
        #pragma unroll
        for (int j = 0; j < 8; j++) {
            int col = n0 + tx * 8 + j;
            float v = acc[i][j];
            if (USE_BIAS) v += bias[col];
            if (USE_SILU) { if (col >= silu_from) v = v / (1.f + __expf(-v)); }
            C[(long long)row * ldc + col] = v;
        }
    }
}

// ---------------- K4: QK-norm + RoPE + scale, V copy ----------------
__global__ void qkv_prep(const float* __restrict__ fused,
                         const float* __restrict__ qn_w, const float* __restrict__ qn_b,
                         const float* __restrict__ kn_w, const float* __restrict__ kn_b) {
    int token = blockIdx.x;
    int head  = blockIdx.y;
    int tid = threadIdx.x;   // 64
    int t  = token / HW;
    int hh = (token / RES) % RES;
    int ww = token % RES;

    __shared__ float s[DH];
    __shared__ float red[64];

    const float* base = fused + (long long)token * NF + head * DH;

    if (tid < DH)
        g_v[((long long)head * THW + token) * DH + tid] = base[2 * DIM + tid];

    for (int which = 0; which < 2; which++) {
        const float* w  = which ? kn_w : qn_w;
        const float* bb = which ? kn_b : qn_b;
        float val = (tid < DH) ? base[which * DIM + tid] : 0.f;

        red[tid] = val; __syncthreads();
        for (int ss = 32; ss > 0; ss >>= 1) { if (tid < ss) red[tid] += red[tid + ss]; __syncthreads(); }
        float mean = red[0] * (1.f / DH);
        __syncthreads();
        float dv = (tid < DH) ? (val - mean) : 0.f;
        red[tid] = dv * dv; __syncthreads();
        for (int ss = 32; ss > 0; ss >>= 1) { if (tid < ss) red[tid] += red[tid + ss]; __syncthreads(); }
        float var = red[0] * (1.f / DH);
        __syncthreads();
        if (tid < DH)
            s[tid] = (val - mean) * rsqrtf(var + EPS) * w[tid] + bb[tid];
        __syncthreads();

        if (tid < DH / 2) {
            int i = tid;
            float x1 = s[2 * i], x2 = s[2 * i + 1];
            float pos = (i < 8) ? (float)t : (i < 16) ? (float)hh : (float)ww;
            int j = i & 7;
            float inv = powf(10000.f, -(float)j * 0.125f);
            float ang = pos * inv;
            float sn, cs;
            sincosf(ang, &sn, &cs);
            float o1 = x1 * cs - x2 * sn;
            float o2 = x1 * sn + x2 * cs;
            float sc = which ? 1.f : 0.14433756729740643f;  // DH^-0.5 on q
            float* dst = (which ? g_k : g_q) + ((long long)head * THW + token) * DH;
            dst[2 * i]     = o1 * sc;
            dst[2 * i + 1] = o2 * sc;
        }
        __syncthreads();
    }
}

// ---------------- K5: neighborhood attention (one block per head,query) ----------------
__global__ void nattn() {
    int token = blockIdx.x;
    int head  = blockIdx.y;
    int tid = threadIdx.x;   // 128
    int h = (token / RES) % RES;
    int w = token % RES;

    __shared__ float q[DH];
    __shared__ float dots[NK];
    __shared__ int   nbr[NK];
    __shared__ float rsum;

    if (tid < DH) q[tid] = g_q[((long long)head * THW + token) * DH + tid];
    __syncthreads();

    if (tid < NK) {
        int a = tid / (KH * KW);
        int c = (tid / KW) % KH;
        int e = tid % KW;
        int sh = min(max(h - KH / 2, 0), RES - KH);
        int sw = min(max(w - KW / 2, 0), RES - KW);
        int ktok = a * HW + (sh + c) * RES + (sw + e);   // kt = a (T==KT)
        nbr[tid] = ktok;
        const float* kp = g_k + ((long long)head * THW + ktok) * DH;
        float d = 0.f;
        #pragma unroll
        for (int i = 0; i < DH; i++) d = fmaf(q[i], kp[i], d);
        dots[tid] = d;
    }
    __syncthreads();

    if (tid == 0) {
        float m = -1e30f;
        for (int j = 0; j < NK; j++) m = fmaxf(m, dots[j]);
        float s = 0.f;
        for (int j = 0; j < NK; j++) { float e = __expf(dots[j] - m); dots[j] = e; s += e; }
        rsum = 1.f / s;
    }
    __syncthreads();

    if (tid < DH) {
        float o = 0.f;
        for (int j = 0; j < NK; j++)
            o = fmaf(dots[j], g_v[((long long)head * THW + nbr[j]) * DH + tid], o);
        g_xa[(long long)token * DIM + head * DH + tid] = o * rsum;
    }
}

// ---------------- K8: skip + attn_out + mlp_out, back to (T, DIM, H, W) ----------------
__global__ void final_add(const float* __restrict__ x, float* __restrict__ out) {
    int gid = blockIdx.x * 256 + threadIdx.x;
    if (gid >= T_ * DIM * HW) return;
    int hw = gid % HW;
    int d  = (gid / HW) % DIM;
    int t  = gid / (DIM * HW);
    int token = t * HW + hw;
    out[gid] = x[gid] + g_attn[(long long)token * DIM + d] + g_mlp[(long long)token * DIM + d];
}

// ---------------- launch ----------------
extern "C" void kernel_launch(void* const* d_in, const int* in_sizes, int n_in,
                              void* d_out, int out_size) {
    const float* x       = (const float*)d_in[0];
    const float* emb     = (const float*)d_in[1];
    const float* w_mod   = (const float*)d_in[2];
    const float* b_mod   = (const float*)d_in[3];
    const float* qn_w    = (const float*)d_in[4];
    const float* qn_b    = (const float*)d_in[5];
    const float* kn_w    = (const float*)d_in[6];
    const float* kn_b    = (const float*)d_in[7];
    const float* W_fused = (const float*)d_in[8];
    const float* b_fused = (const float*)d_in[9];
    const float* W_out   = (const float*)d_in[10];
    const float* W_mlp   = (const float*)d_in[11];
    const float* b_mlp   = (const float*)d_in[12];
    float* out = (float*)d_out;

    float *p_h, *p_fused, *p_xa, *p_attn, *p_mlp;
    cudaGetSymbolAddress((void**)&p_h,     g_h);
    cudaGetSymbolAddress((void**)&p_fused, g_fused);
    cudaGetSymbolAddress((void**)&p_xa,    g_xa);
    cudaGetSymbolAddress((void**)&p_attn,  g_attn);
    cudaGetSymbolAddress((void**)&p_mlp,   g_mlp);

    // K1: modulation vectors (per t)
    mod_kernel<<<T_ * 6, 256>>>(emb, w_mod, b_mod);
    // K2: LN + modulate
    ln_mod_kernel<<<THW, 256>>>(x);
    // K3: fused = h @ W_fused + b ; silu on mlp slice (cols >= 2304)
    sgemm<1, 1><<<dim3(NF / 128, (THW + 127) / 128), 256>>>(
        p_h, DIM, W_fused, b_fused, p_fused, NF, THW, NF, DIM, 3 * DIM);
    // K4: qk-norm + rope + scale, v copy
    qkv_prep<<<dim3(THW, HEADS), 64>>>(p_fused, qn_w, qn_b, kn_w, kn_b);
    // K5: neighborhood attention
    nattn<<<dim3(THW, HEADS), 128>>>();
    // K6: attn_out = xa @ W_out
    sgemm<0, 0><<<dim3(DIM / 128, (THW + 127) / 128), 256>>>(
        p_xa, DIM, W_out, nullptr, p_attn, DIM, THW, DIM, DIM, 0);
    // K7: mlp_out = silu(mlp_h) @ W_mlp + b_mlp  (silu already applied in K3 epilogue)
    sgemm<1, 0><<<dim3(DIM / 128, (THW + 127) / 128), 256>>>(
        p_fused + 3 * DIM, NF, W_mlp, b_mlp, p_mlp, DIM, THW, DIM, MLP, 0);
    // K8: combine + layout back
    final_add<<<(T_ * DIM * HW + 255) / 256, 256>>>(x, out);
}

// round 2
// speedup vs baseline: 1.9253x; 1.9253x over previous
#include <cuda_runtime.h>
#include <math.h>

// ---------------- problem constants ----------------
#define DIM   768
#define HEADS 16
#define DH    48
#define EMB   1024
#define T_    3
#define RES   24
#define HW    (RES*RES)        // 576
#define THW   (T_*HW)          // 1728
#define MLP   (4*DIM)          // 3072
#define NF    (3*DIM + MLP)    // 5376
#define KT    3
#define KH    5
#define KW    5
#define NK    (KT*KH*KW)       // 75
#define EPS   1e-5f

// ---------------- scratch (static device allocs) ----------------
__device__ float g_mod  [T_ * 2 * DIM];
__device__ float g_h    [THW * DIM];
__device__ float g_fused[THW * NF];
__device__ float g_q    [HEADS * THW * DH];
__device__ float g_k    [HEADS * THW * DH];
__device__ float g_v    [HEADS * THW * DH];
__device__ float g_xa   [THW * DIM];
__device__ float g_attn [THW * DIM];
__device__ float g_mlp  [THW * DIM];

// ---------------- K1: mod = silu(emb) @ w_mod + b_mod  (3 x 1536) ----------------
__global__ void mod_kernel(const float* __restrict__ emb,
                           const float* __restrict__ w_mod,
                           const float* __restrict__ b_mod) {
    int t = blockIdx.x / 6;
    int n = (blockIdx.x % 6) * 256 + threadIdx.x;
    __shared__ float se[EMB];
    for (int i = threadIdx.x; i < EMB; i += 256) {
        float e = emb[t * EMB + i];
        se[i] = e / (1.f + __expf(-e));
    }
    __syncthreads();
    float acc = b_mod[n];
    for (int e = 0; e < EMB; e++)
        acc += se[e] * w_mod[e * (2 * DIM) + n];
    g_mod[t * (2 * DIM) + n] = acc;
}

// ---------------- K2: per-token LN + modulate ----------------
__global__ void ln_mod_kernel(const float* __restrict__ x) {
    int token = blockIdx.x;
    int t  = token / HW;
    int hw = token % HW;
    int tid = threadIdx.x;
    __shared__ float red[256];

    float v[3];
    float sum = 0.f;
    #pragma unroll
    for (int i = 0; i < 3; i++) {
        int d = tid + i * 256;
        v[i] = x[((t * DIM) + d) * HW + hw];
        sum += v[i];
    }
    red[tid] = sum; __syncthreads();
    for (int s = 128; s > 0; s >>= 1) { if (tid < s) red[tid] += red[tid + s]; __syncthreads(); }
    float mean = red[0] * (1.f / DIM);
    __syncthreads();

    float sq = 0.f;
    #pragma unroll
    for (int i = 0; i < 3; i++) { float d = v[i] - mean; sq += d * d; }
    red[tid] = sq; __syncthreads();
    for (int s = 128; s > 0; s >>= 1) { if (tid < s) red[tid] += red[tid + s]; __syncthreads(); }
    float var = red[0] * (1.f / DIM);
    float rstd = rsqrtf(var + EPS);

    #pragma unroll
    for (int i = 0; i < 3; i++) {
        int d = tid + i * 256;
        float y = (v[i] - mean) * rstd;
        float scale = g_mod[t * (2 * DIM) + d];
        float shift = g_mod[t * (2 * DIM) + DIM + d];
        g_h[token * DIM + d] = y * (1.f + scale) + shift;
    }
}

// ---------------- TF32 tensor-core GEMM ----------------
// C[M,N] = A[M,K](lda) @ B[K,N](row major N stride) (+bias) (+silu cols>=silu_from)
// BM=BN=128, BK=16, 256 threads (8 warps, 4x2), warp tile 32x64, mma.m16n8k8.
#define SA 138   // As row stride (floats): k-major, STS conflict-free, LDS near-free
#define SB 136   // Bs row stride (floats): 16B-aligned rows, conflict-free

__device__ __forceinline__ unsigned f2tf(float x) {
    unsigned u; asm("cvt.rna.tf32.f32 %0, %1;" : "=r"(u) : "f"(x)); return u;
}
__device__ __forceinline__ void mma8(float* c, unsigned a0, unsigned a1, unsigned a2, unsigned a3,
                                     unsigned b0, unsigned b1) {
    asm volatile("mma.sync.aligned.m16n8k8.row.col.f32.tf32.tf32.f32 "
                 "{%0,%1,%2,%3},{%4,%5,%6,%7},{%8,%9},{%0,%1,%2,%3};"
                 : "+f"(c[0]), "+f"(c[1]), "+f"(c[2]), "+f"(c[3])
                 : "r"(a0), "r"(a1), "r"(a2), "r"(a3), "r"(b0), "r"(b1));
}

template<int USE_BIAS, int USE_SILU>
__global__ void __launch_bounds__(256)
tf32gemm(const float* __restrict__ A, int lda,
         const float* __restrict__ B,
         const float* __restrict__ bias,
         float* __restrict__ C, int ldc,
         int M, int N, int K, int silu_from)
{
    __shared__ float As[2][16][SA];
    __shared__ float Bs[2][16][SB];

    const int tid  = threadIdx.x;
    const int lane = tid & 31;
    const int wid  = tid >> 5;
    const int wm   = wid & 3;        // 4 warps along M
    const int wn   = wid >> 2;       // 2 warps along N
    const int lr   = lane >> 2;      // 0..7
    const int lc   = lane & 3;       // 0..3
    const int m0   = blockIdx.y * 128;
    const int n0   = blockIdx.x * 128;

    // global-load mapping
    const int ar  = tid >> 2;            // 0..63 (A rows; +64 for second chunk)
    const int ac  = (tid & 3) * 4;       // A col group within BK
    const int br  = tid >> 5;            // 0..7  (B rows; +8 for second)
    const int bc  = (tid & 31) * 4;      // B col group
    const float4 z4 = make_float4(0.f, 0.f, 0.f, 0.f);

    float acc[2][8][4];
    #pragma unroll
    for (int i = 0; i < 2; i++)
        #pragma unroll
        for (int j = 0; j < 8; j++)
            #pragma unroll
            for (int q = 0; q < 4; q++) acc[i][j][q] = 0.f;

    const int kTiles = K / 16;

    float4 pa0, pa1, pb0, pb1;
    // prefetch tile 0
    {
        int k0 = 0;
        pa0 = (m0 + ar      < M) ? *(const float4*)(A + (long long)(m0 + ar)      * lda + k0 + ac) : z4;
        pa1 = (m0 + 64 + ar < M) ? *(const float4*)(A + (long long)(m0 + 64 + ar) * lda + k0 + ac) : z4;
        pb0 = *(const float4*)(B + (long long)(k0 + br)     * N + n0 + bc);
        pb1 = *(const float4*)(B + (long long)(k0 + br + 8) * N + n0 + bc);
    }
    // store tile 0 -> buf 0
    {
        As[0][ac + 0][ar] = __uint_as_float(f2tf(pa0.x));
        As[0][ac + 1][ar] = __uint_as_float(f2tf(pa0.y));
        As[0][ac + 2][ar] = __uint_as_float(f2tf(pa0.z));
        As[0][ac + 3][ar] = __uint_as_float(f2tf(pa0.w));
        As[0][ac + 0][ar + 64] = __uint_as_float(f2tf(pa1.x));
        As[0][ac + 1][ar + 64] = __uint_as_float(f2tf(pa1.y));
        As[0][ac + 2][ar + 64] = __uint_as_float(f2tf(pa1.z));
        As[0][ac + 3][ar + 64] = __uint_as_float(f2tf(pa1.w));
        float4 t0 = make_float4(__uint_as_float(f2tf(pb0.x)), __uint_as_float(f2tf(pb0.y)),
                                __uint_as_float(f2tf(pb0.z)), __uint_as_float(f2tf(pb0.w)));
        float4 t1 = make_float4(__uint_as_float(f2tf(pb1.x)), __uint_as_float(f2tf(pb1.y)),
                                __uint_as_float(f2tf(pb1.z)), __uint_as_float(f2tf(pb1.w)));
        *(float4*)&Bs[0][br][bc]     = t0;
        *(float4*)&Bs[0][br + 8][bc] = t1;
    }
    __syncthreads();

    int buf = 0;
    for (int kt = 0; kt < kTiles; kt++) {
        // prefetch next tile into registers
        if (kt + 1 < kTiles) {
            int k0 = (kt + 1) * 16;
            pa0 = (m0 + ar      < M) ? *(const float4*)(A + (long long)(m0 + ar)      * lda + k0 + ac) : z4;
            pa1 = (m0 + 64 + ar < M) ? *(const float4*)(A + (long long)(m0 + 64 + ar) * lda + k0 + ac) : z4;
            pb0 = *(const float4*)(B + (long long)(k0 + br)     * N + n0 + bc);
            pb1 = *(const float4*)(B + (long long)(k0 + br + 8) * N + n0 + bc);
        }

        // compute on current buffer
        #pragma unroll
        for (int kk = 0; kk < 16; kk += 8) {
            unsigned af[2][4];
            #pragma unroll
            for (int i = 0; i < 2; i++) {
                int row = wm * 32 + i * 16 + lr;
                af[i][0] = __float_as_uint(As[buf][kk + lc][row]);
                af[i][1] = __float_as_uint(As[buf][kk + lc][row + 8]);
                af[i][2] = __float_as_uint(As[buf][kk + lc + 4][row]);
                af[i][3] = __float_as_uint(As[buf][kk + lc + 4][row + 8]);
            }
            #pragma unroll
            for (int j = 0; j < 8; j++) {
                int col = wn * 64 + j * 8 + lr;
                unsigned b0 = __float_as_uint(Bs[buf][kk + lc][col]);
                unsigned b1 = __float_as_uint(Bs[buf][kk + lc + 4][col]);
                mma8(acc[0][j], af[0][0], af[0][1], af[0][2], af[0][3], b0, b1);
                mma8(acc[1][j], af[1][0], af[1][1], af[1][2], af[1][3], b0, b1);
            }
        }

        // store prefetched tile to other buffer
        if (kt + 1 < kTiles) {
            int nb = buf ^ 1;
            As[nb][ac + 0][ar] = __uint_as_float(f2tf(pa0.x));
            As[nb][ac + 1][ar] = __uint_as_float(f2tf(pa0.y));
            As[nb][ac + 2][ar] = __uint_as_float(f2tf(pa0.z));
            As[nb][ac + 3][ar] = __uint_as_float(f2tf(pa0.w));
            As[nb][ac + 0][ar + 64] = __uint_as_float(f2tf(pa1.x));
            As[nb][ac + 1][ar + 64] = __uint_as_float(f2tf(pa1.y));
            As[nb][ac + 2][ar + 64] = __uint_as_float(f2tf(pa1.z));
            As[nb][ac + 3][ar + 64] = __uint_as_float(f2tf(pa1.w));
            float4 t0 = make_float4(__uint_as_float(f2tf(pb0.x)), __uint_as_float(f2tf(pb0.y)),
                                    __uint_as_float(f2tf(pb0.z)), __uint_as_float(f2tf(pb0.w)));
            float4 t1 = make_float4(__uint_as_float(f2tf(pb1.x)), __uint_as_float(f2tf(pb1.y)),
                                    __uint_as_float(f2tf(pb1.z)), __uint_as_float(f2tf(pb1.w)));
            *(float4*)&Bs[nb][br][bc]     = t0;
            *(float4*)&Bs[nb][br + 8][bc] = t1;
            __syncthreads();
            buf = nb;
        }
    }

    // epilogue
    #pragma unroll
    for (int i = 0; i < 2; i++) {
        #pragma unroll
        for (int j = 0; j < 8; j++) {
            int row = m0 + wm * 32 + i * 16 + lr;
            int col = n0 + wn * 64 + j * 8 + 2 * lc;
            #pragma unroll
            for (int h = 0; h < 2; h++) {       // h=0: rows row, h=1: row+8
                int r = row + h * 8;
                if (r >= M) continue;
                #pragma unroll
                for (int q = 0; q < 2; q++) {
                    int cidx = col + q;
                    float v = acc[i][j][h * 2 + q];
                    if (USE_BIAS) v += bias[cidx];
                    if (USE_SILU) { if (cidx >= silu_from) v = v / (1.f + __expf(-v)); }
                    C[(long long)r * ldc + cidx] = v;
                }
            }
        }
    }
}

// ---------------- K4: QK-norm + RoPE + scale, V copy ----------------
__global__ void qkv_prep(const float* __restrict__ fused,
                         const float* __restrict__ qn_w, const float* __restrict__ qn_b,
                         const float* __restrict__ kn_w, const float* __restrict__ kn_b) {
    int token = blockIdx.x;
    int head  = blockIdx.y;
    int tid = threadIdx.x;   // 64
    int t  = token / HW;
    int hh = (token / RES) % RES;
    int ww = token % RES;

    __shared__ float s[DH];
    __shared__ float red[64];

    const float* base = fused + (long long)token * NF + head * DH;

    if (tid < DH)
        g_v[((long long)head * THW + token) * DH + tid] = base[2 * DIM + tid];

    for (int which = 0; which < 2; which++) {
        const float* w  = which ? kn_w : qn_w;
        const float* bb = which ? kn_b : qn_b;
        float val = (tid < DH) ? base[which * DIM + tid] : 0.f;

        red[tid] = val; __syncthreads();
        for (int ss = 32; ss > 0; ss >>= 1) { if (tid < ss) red[tid] += red[tid + ss]; __syncthreads(); }
        float mean = red[0] * (1.f / DH);
        __syncthreads();
        float dv = (tid < DH) ? (val - mean) : 0.f;
        red[tid] = dv * dv; __syncthreads();
        for (int ss = 32; ss > 0; ss >>= 1) { if (tid < ss) red[tid] += red[tid + ss]; __syncthreads(); }
        float var = red[0] * (1.f / DH);
        __syncthreads();
        if (tid < DH)
            s[tid] = (val - mean) * rsqrtf(var + EPS) * w[tid] + bb[tid];
        __syncthreads();

        if (tid < DH / 2) {
            int i = tid;
            float x1 = s[2 * i], x2 = s[2 * i + 1];
            float pos = (i < 8) ? (float)t : (i < 16) ? (float)hh : (float)ww;
            int j = i & 7;
            float inv = powf(10000.f, -(float)j * 0.125f);
            float ang = pos * inv;
            float sn, cs;
            sincosf(ang, &sn, &cs);
            float o1 = x1 * cs - x2 * sn;
            float o2 = x1 * sn + x2 * cs;
            float sc = which ? 1.f : 0.14433756729740643f;
            float* dst = (which ? g_k : g_q) + ((long long)head * THW + token) * DH;
            dst[2 * i]     = o1 * sc;
            dst[2 * i + 1] = o2 * sc;
        }
        __syncthreads();
    }
}

// ---------------- K5: neighborhood attention ----------------
__global__ void nattn() {
    int token = blockIdx.x;
    int head  = blockIdx.y;
    int tid = threadIdx.x;   // 128
    int h = (token / RES) % RES;
    int w = token % RES;

    __shared__ float q[DH];
    __shared__ float dots[NK];
    __shared__ int   nbr[NK];
    __shared__ float rsum;

    if (tid < DH) q[tid] = g_q[((long long)head * THW + token) * DH + tid];
    __syncthreads();

    if (tid < NK) {
        int a = tid / (KH * KW);
        int c = (tid / KW) % KH;
        int e = tid % KW;
        int sh = min(max(h - KH / 2, 0), RES - KH);
        int sw = min(max(w - KW / 2, 0), RES - KW);
        int ktok = a * HW + (sh + c) * RES + (sw + e);
        nbr[tid] = ktok;
        const float* kp = g_k + ((long long)head * THW + ktok) * DH;
        float d = 0.f;
        #pragma unroll
        for (int i = 0; i < DH; i++) d = fmaf(q[i], kp[i], d);
        dots[tid] = d;
    }
    __syncthreads();

    if (tid == 0) {
        float m = -1e30f;
        for (int j = 0; j < NK; j++) m = fmaxf(m, dots[j]);
        float s = 0.f;
        for (int j = 0; j < NK; j++) { float e = __expf(dots[j] - m); dots[j] = e; s += e; }
        rsum = 1.f / s;
    }
    __syncthreads();

    if (tid < DH) {
        float o = 0.f;
        for (int j = 0; j < NK; j++)
            o = fmaf(dots[j], g_v[((long long)head * THW + nbr[j]) * DH + tid], o);
        g_xa[(long long)token * DIM + head * DH + tid] = o * rsum;
    }
}

// ---------------- K8: skip + attn_out + mlp_out ----------------
__global__ void final_add(const float* __restrict__ x, float* __restrict__ out) {
    int gid = blockIdx.x * 256 + threadIdx.x;
    if (gid >= T_ * DIM * HW) return;
    int hw = gid % HW;
    int d  = (gid / HW) % DIM;
    int t  = gid / (DIM * HW);
    int token = t * HW + hw;
    out[gid] = x[gid] + g_attn[(long long)token * DIM + d] + g_mlp[(long long)token * DIM + d];
}

// ---------------- launch ----------------
extern "C" void kernel_launch(void* const* d_in, const int* in_sizes, int n_in,
                              void* d_out, int out_size) {
    const float* x       = (const float*)d_in[0];
    const float* emb     = (const float*)d_in[1];
    const float* w_mod   = (const float*)d_in[2];
    const float* b_mod   = (const float*)d_in[3];
    const float* qn_w    = (const float*)d_in[4];
    const float* qn_b    = (const float*)d_in[5];
    const float* kn_w    = (const float*)d_in[6];
    const float* kn_b    = (const float*)d_in[7];
    const float* W_fused = (const float*)d_in[8];
    const float* b_fused = (const float*)d_in[9];
    const float* W_out   = (const float*)d_in[10];
    const float* W_mlp   = (const float*)d_in[11];
    const float* b_mlp   = (const float*)d_in[12];
    float* out = (float*)d_out;

    float *p_h, *p_fused, *p_xa, *p_attn, *p_mlp;
    cudaGetSymbolAddress((void**)&p_h,     g_h);
    cudaGetSymbolAddress((void**)&p_fused, g_fused);
    cudaGetSymbolAddress((void**)&p_xa,    g_xa);
    cudaGetSymbolAddress((void**)&p_attn,  g_attn);
    cudaGetSymbolAddress((void**)&p_mlp,   g_mlp);

    mod_kernel<<<T_ * 6, 256>>>(emb, w_mod, b_mod);
    ln_mod_kernel<<<THW, 256>>>(x);
    // fused = h @ W_fused + b ; silu on mlp slice
    tf32gemm<1, 1><<<dim3(NF / 128, (THW + 127) / 128), 256>>>(
        p_h, DIM, W_fused, b_fused, p_fused, NF, THW, NF, DIM, 3 * DIM);
    qkv_prep<<<dim3(THW, HEADS), 64>>>(p_fused, qn_w, qn_b, kn_w, kn_b);
    nattn<<<dim3(THW, HEADS), 128>>>();
    // attn_out = xa @ W_out
    tf32gemm<0, 0><<<dim3(DIM / 128, (THW + 127) / 128), 256>>>(
        p_xa, DIM, W_out, nullptr, p_attn, DIM, THW, DIM, DIM, 0);
    // mlp_out = silu(mlp_h) @ W_mlp + b_mlp
    tf32gemm<1, 0><<<dim3(DIM / 128, (THW + 127) / 128), 256>>>(
        p_fused + 3 * DIM, NF, W_mlp, b_mlp, p_mlp, DIM, THW, DIM, MLP, 0);
    final_add<<<(T_ * DIM * HW + 255) / 256, 256>>>(x, out);
}

// round 3
// speedup vs baseline: 3.2270x; 1.6761x over previous
#include <cuda_runtime.h>
#include <math.h>

// ---------------- problem constants ----------------
#define DIM   768
#define HEADS 16
#define DH    48
#define EMB   1024
#define T_    3
#define RES   24
#define HW    (RES*RES)        // 576
#define THW   (T_*HW)          // 1728
#define MLP   (4*DIM)          // 3072
#define NF    (3*DIM + MLP)    // 5376
#define KT    3
#define KH    5
#define KW    5
#define NK    (KT*KH*KW)       // 75
#define EPS   1e-5f

// ---------------- scratch ----------------
__device__ float g_mod  [T_ * 2 * DIM];
__device__ float g_h    [THW * DIM];
__device__ float g_fused[THW * NF];
__device__ float g_q    [HEADS * THW * DH];
__device__ float g_k    [HEADS * THW * DH];
__device__ float g_v    [HEADS * THW * DH];
__device__ float g_xa   [THW * DIM];
__device__ float g_attn [THW * DIM];

// ---------------- K1: mod = silu(emb) @ w_mod + b_mod ----------------
__global__ void mod_kernel(const float* __restrict__ emb,
                           const float* __restrict__ w_mod,
                           const float* __restrict__ b_mod) {
    int t = blockIdx.x / 6;
    int n = (blockIdx.x % 6) * 256 + threadIdx.x;
    __shared__ float se[EMB];
    for (int i = threadIdx.x; i < EMB; i += 256) {
        float e = emb[t * EMB + i];
        se[i] = e / (1.f + __expf(-e));
    }
    __syncthreads();
    float acc = b_mod[n];
    for (int e = 0; e < EMB; e++)
        acc += se[e] * w_mod[e * (2 * DIM) + n];
    g_mod[t * (2 * DIM) + n] = acc;
}

// ---------------- K2: per-token LN + modulate ----------------
__global__ void ln_mod_kernel(const float* __restrict__ x) {
    int token = blockIdx.x;
    int t  = token / HW;
    int hw = token % HW;
    int tid = threadIdx.x;
    __shared__ float red[256];

    float v[3];
    float sum = 0.f;
    #pragma unroll
    for (int i = 0; i < 3; i++) {
        int d = tid + i * 256;
        v[i] = x[((t * DIM) + d) * HW + hw];
        sum += v[i];
    }
    red[tid] = sum; __syncthreads();
    for (int s = 128; s > 0; s >>= 1) { if (tid < s) red[tid] += red[tid + s]; __syncthreads(); }
    float mean = red[0] * (1.f / DIM);
    __syncthreads();

    float sq = 0.f;
    #pragma unroll
    for (int i = 0; i < 3; i++) { float d = v[i] - mean; sq += d * d; }
    red[tid] = sq; __syncthreads();
    for (int s = 128; s > 0; s >>= 1) { if (tid < s) red[tid] += red[tid + s]; __syncthreads(); }
    float var = red[0] * (1.f / DIM);
    float rstd = rsqrtf(var + EPS);

    #pragma unroll
    for (int i = 0; i < 3; i++) {
        int d = tid + i * 256;
        float y = (v[i] - mean) * rstd;
        float scale = g_mod[t * (2 * DIM) + d];
        float shift = g_mod[t * (2 * DIM) + DIM + d];
        g_h[token * DIM + d] = y * (1.f + scale) + shift;
    }
}

// ---------------- TF32 tensor GEMM, cp.async 3-stage, BK=32 ----------------
// MODE 0: plain   1: +bias   2: +bias, silu for col>=silu_from
// MODE 3: final:  out[(t*DIM+col)*HW+hw] = acc + bias[col] + attn[r*DIM+col] + x[(t*DIM+col)*HW+hw]
#define GSTAGES 3
#define AS_STRIDE 36
#define BS_STRIDE 136
#define GEMM_SMEM (GSTAGES * (128*AS_STRIDE + 32*BS_STRIDE) * 4)

__device__ __forceinline__ unsigned smem_u32p(const void* p) {
    return (unsigned)__cvta_generic_to_shared(p);
}
__device__ __forceinline__ void mma8(float* c, unsigned a0, unsigned a1, unsigned a2, unsigned a3,
                                     unsigned b0, unsigned b1) {
    asm volatile("mma.sync.aligned.m16n8k8.row.col.f32.tf32.tf32.f32 "
                 "{%0,%1,%2,%3},{%4,%5,%6,%7},{%8,%9},{%0,%1,%2,%3};"
                 : "+f"(c[0]), "+f"(c[1]), "+f"(c[2]), "+f"(c[3])
                 : "r"(a0), "r"(a1), "r"(a2), "r"(a3), "r"(b0), "r"(b1));
}

template<int MODE>
__global__ void __launch_bounds__(256)
tf32gemm(const float* __restrict__ A, int lda,
         const float* __restrict__ B,
         const float* __restrict__ bias,
         float* __restrict__ C, int ldc,
         int M, int N, int K, int silu_from,
         const float* __restrict__ attn, const float* __restrict__ xres)
{
    extern __shared__ float sm[];
    float* Asm = sm;                               // [stage][128][AS_STRIDE]
    float* Bsm = sm + GSTAGES * 128 * AS_STRIDE;   // [stage][32][BS_STRIDE]

    const int tid  = threadIdx.x;
    const int lane = tid & 31;
    const int wid  = tid >> 5;
    const int wm   = wid & 3;
    const int wn   = wid >> 2;
    const int lr   = lane >> 2;
    const int lc   = lane & 3;
    const int m0   = blockIdx.y * 128;
    const int n0   = blockIdx.x * 128;

    float acc[2][8][4];
    #pragma unroll
    for (int i = 0; i < 2; i++)
        #pragma unroll
        for (int j = 0; j < 8; j++)
            #pragma unroll
            for (int q = 0; q < 4; q++) acc[i][j][q] = 0.f;

    const int kTiles = K / 32;

    // ---- stage loader ----
    auto load_stage = [&](int kt, int st) {
        int k0 = kt * 32;
        float* as = Asm + st * 128 * AS_STRIDE;
        float* bs = Bsm + st * 32 * BS_STRIDE;
        #pragma unroll
        for (int r = 0; r < 4; r++) {
            int cid = tid + 256 * r;
            int m  = cid >> 3;
            int kc = (cid & 7) * 4;
            const float* src = A + (long long)(m0 + m) * lda + k0 + kc;
            unsigned dst = smem_u32p(as + m * AS_STRIDE + kc);
            int sz = ((m0 + m) < M) ? 16 : 0;
            asm volatile("cp.async.cg.shared.global [%0],[%1],16,%2;\n"
                         :: "r"(dst), "l"(src), "r"(sz));
        }
        #pragma unroll
        for (int r = 0; r < 4; r++) {
            int cid = tid + 256 * r;
            int k  = cid >> 5;
            int n4 = (cid & 31) * 4;
            const float* src = B + (long long)(k0 + k) * N + n0 + n4;
            unsigned dst = smem_u32p(bs + k * BS_STRIDE + n4);
            asm volatile("cp.async.cg.shared.global [%0],[%1],16,16;\n"
                         :: "r"(dst), "l"(src));
        }
        asm volatile("cp.async.commit_group;\n");
    };

    // prologue: stages 0..GSTAGES-2
    #pragma unroll
    for (int s = 0; s < GSTAGES - 1; s++) load_stage(s, s);

    for (int kt = 0; kt < kTiles; kt++) {
        if (kt + GSTAGES - 1 < kTiles)
            load_stage(kt + GSTAGES - 1, (kt + GSTAGES - 1) % GSTAGES);
        else
            asm volatile("cp.async.commit_group;\n");

        asm volatile("cp.async.wait_group %0;\n" :: "n"(GSTAGES - 2));
        __syncthreads();

        const float* as = Asm + (kt % GSTAGES) * 128 * AS_STRIDE;
        const float* bs = Bsm + (kt % GSTAGES) * 32 * BS_STRIDE;

        #pragma unroll
        for (int kk = 0; kk < 32; kk += 8) {
            unsigned af[2][4];
            #pragma unroll
            for (int i = 0; i < 2; i++) {
                int row = wm * 32 + i * 16 + lr;
                af[i][0] = __float_as_uint(as[row * AS_STRIDE + kk + lc]);
                af[i][1] = __float_as_uint(as[(row + 8) * AS_STRIDE + kk + lc]);
                af[i][2] = __float_as_uint(as[row * AS_STRIDE + kk + lc + 4]);
                af[i][3] = __float_as_uint(as[(row + 8) * AS_STRIDE + kk + lc + 4]);
            }
            #pragma unroll
            for (int j = 0; j < 8; j++) {
                int col = wn * 64 + j * 8 + lr;
                unsigned b0 = __float_as_uint(bs[(kk + lc) * BS_STRIDE + col]);
                unsigned b1 = __float_as_uint(bs[(kk + lc + 4) * BS_STRIDE + col]);
                mma8(acc[0][j], af[0][0], af[0][1], af[0][2], af[0][3], b0, b1);
                mma8(acc[1][j], af[1][0], af[1][1], af[1][2], af[1][3], b0, b1);
            }
        }
        __syncthreads();
    }

    // epilogue
    #pragma unroll
    for (int i = 0; i < 2; i++) {
        #pragma unroll
        for (int j = 0; j < 8; j++) {
            #pragma unroll
            for (int h = 0; h < 2; h++) {
                int r = m0 + wm * 32 + i * 16 + lr + h * 8;
                if (r >= M) continue;
                #pragma unroll
                for (int q = 0; q < 2; q++) {
                    int cidx = n0 + wn * 64 + j * 8 + 2 * lc + q;
                    float v = acc[i][j][h * 2 + q];
                    if (MODE >= 1) v += bias[cidx];
                    if (MODE == 2) { if (cidx >= silu_from) v = v / (1.f + __expf(-v)); }
                    if (MODE == 3) {
                        int t  = r / HW;
                        int hw = r % HW;
                        long long oidx = ((long long)t * DIM + cidx) * HW + hw;
                        v += attn[(long long)r * DIM + cidx] + xres[oidx];
                        C[oidx] = v;
                    } else {
                        C[(long long)r * ldc + cidx] = v;
                    }
                }
            }
        }
    }
}

// ---------------- K4: warp-per-(token,head) QK-norm + RoPE, V copy ----------------
__global__ void qkv_warp(const float* __restrict__ fused,
                         const float* __restrict__ qn_w, const float* __restrict__ qn_b,
                         const float* __restrict__ kn_w, const float* __restrict__ kn_b) {
    int wid  = threadIdx.x >> 5;
    int lane = threadIdx.x & 31;
    int gw = blockIdx.x * 8 + wid;        // warp id over THW*HEADS
    int token = gw >> 4;
    int head  = gw & 15;
    int t  = token / HW;
    int hh = (token / RES) % RES;
    int ww = token % RES;

    __shared__ float s_all[8][DH];
    float* s = s_all[wid];

    const float* base = fused + (long long)token * NF + head * DH;

    // V copy
    {
        float v0 = base[2 * DIM + lane];
        g_v[((long long)head * THW + token) * DH + lane] = v0;
        if (lane < 16)
            g_v[((long long)head * THW + token) * DH + 32 + lane] = base[2 * DIM + 32 + lane];
    }

    #pragma unroll
    for (int which = 0; which < 2; which++) {
        const float* w  = which ? kn_w : qn_w;
        const float* bb = which ? kn_b : qn_b;
        float v0 = base[which * DIM + lane];
        float v1 = (lane < 16) ? base[which * DIM + 32 + lane] : 0.f;

        float sum = v0 + v1;
        #pragma unroll
        for (int o = 16; o > 0; o >>= 1) sum += __shfl_xor_sync(0xffffffffu, sum, o);
        float mean = sum * (1.f / DH);

        float d0 = v0 - mean;
        float d1 = (lane < 16) ? (v1 - mean) : 0.f;
        float sq = d0 * d0 + d1 * d1;
        #pragma unroll
        for (int o = 16; o > 0; o >>= 1) sq += __shfl_xor_sync(0xffffffffu, sq, o);
        float rstd = rsqrtf(sq * (1.f / DH) + EPS);

        s[lane] = d0 * rstd * w[lane] + bb[lane];
        if (lane < 16)
            s[32 + lane] = d1 * rstd * w[32 + lane] + bb[32 + lane];
        __syncwarp();

        if (lane < DH / 2) {
            int i = lane;
            float x1 = s[2 * i], x2 = s[2 * i + 1];
            float pos = (i < 8) ? (float)t : (i < 16) ? (float)hh : (float)ww;
            int j = i & 7;
            float inv = powf(10000.f, -(float)j * 0.125f);
            float ang = pos * inv;
            float sn, cs;
            sincosf(ang, &sn, &cs);
            float o1 = x1 * cs - x2 * sn;
            float o2 = x1 * sn + x2 * cs;
            float sc = which ? 1.f : 0.14433756729740643f;
            float* dst = (which ? g_k : g_q) + ((long long)head * THW + token) * DH;
            dst[2 * i]     = o1 * sc;
            dst[2 * i + 1] = o2 * sc;
        }
        __syncwarp();
    }
}

// ---------------- K5: tiled neighborhood attention ----------------
// grid (9 tiles, 16 heads), 256 threads; smem holds 3x12x12 K/V union + 192 queries.
#define UTOK 432            // 3*12*12
#define KSTRIDE 50          // token row stride (floats), float2 aligned, odd/32-friendly
#define NA_SMEM ((2*UTOK*KSTRIDE + 192*DH + 8*80) * 4 + 8*80*4)

__global__ void __launch_bounds__(256)
nattn_tiled() {
    extern __shared__ float sm[];
    float* Ks = sm;                          // [432][50]
    float* Vs = Ks + UTOK * KSTRIDE;
    float* Qs = Vs + UTOK * KSTRIDE;         // [192][48]
    float* Ps = Qs + 192 * DH;               // [8][80] probs
    int*   Ts = (int*)(Ps + 8 * 80);         // [8][80] token idx

    const int tile = blockIdx.x;             // 0..8
    const int head = blockIdx.y;
    const int th0 = (tile / 3) * 8;
    const int tw0 = (tile % 3) * 8;
    const int kh0 = min(max(th0 - 2, 0), RES - 12);
    const int kw0 = min(max(tw0 - 2, 0), RES - 12);
    const int tid  = threadIdx.x;
    const int wid  = tid >> 5;
    const int lane = tid & 31;

    const float* kbase = g_k + (long long)head * THW * DH;
    const float* vbase = g_v + (long long)head * THW * DH;
    const float* qbase = g_q + (long long)head * THW * DH;

    // load K/V union tile (float2)
    for (int i = tid; i < UTOK * 24; i += 256) {
        int tok = i / 24, u = i % 24;
        int kt = tok / 144, rem = tok % 144;
        int rr = rem / 12, cc = rem % 12;
        int gtok = kt * HW + (kh0 + rr) * RES + (kw0 + cc);
        float2 kv = *(const float2*)(kbase + (long long)gtok * DH + 2 * u);
        float2 vv = *(const float2*)(vbase + (long long)gtok * DH + 2 * u);
        *(float2*)&Ks[tok * KSTRIDE + 2 * u] = kv;
        *(float2*)&Vs[tok * KSTRIDE + 2 * u] = vv;
    }
    // load Q tile
    for (int i = tid; i < 192 * 24; i += 256) {
        int qi = i / 24, u = i % 24;
        int t = qi / 64, rem = qi % 64;
        int qr = rem / 8, qc = rem % 8;
        int gtok = t * HW + (th0 + qr) * RES + (tw0 + qc);
        *(float2*)&Qs[qi * DH + 2 * u] = *(const float2*)(qbase + (long long)gtok * DH + 2 * u);
    }
    __syncthreads();

    // each warp: 24 queries
    for (int it = 0; it < 24; it++) {
        int qi = wid * 24 + it;
        int t = qi / 64, rem = qi % 64;
        int qr = rem / 8, qc = rem % 8;
        int hq = th0 + qr, wq = tw0 + qc;
        int rb = min(max(hq - 2, 0), RES - KH) - kh0;
        int cb = min(max(wq - 2, 0), RES - KW) - kw0;
        const float* qs = Qs + qi * DH;

        // dots: lane handles keys lane, lane+32, lane+64
        float d[3] = {-1e30f, -1e30f, -1e30f};
        int   tk[3] = {0, 0, 0};
        #pragma unroll
        for (int c = 0; c < 3; c++) {
            int s = lane + 32 * c;
            if (s < NK) {
                int kt = s / 25, r2 = (s % 25) / 5, c2 = s % 5;
                int tok = kt * 144 + (rb + r2) * 12 + (cb + c2);
                tk[c] = tok;
                const float* kp = Ks + tok * KSTRIDE;
                float acc = 0.f;
                #pragma unroll
                for (int u = 0; u < 24; u++) {
                    float2 qv = *(const float2*)(qs + 2 * u);
                    float2 kv = *(const float2*)(kp + 2 * u);
                    acc = fmaf(qv.x, kv.x, acc);
                    acc = fmaf(qv.y, kv.y, acc);
                }
                d[c] = acc;
            }
        }
        // softmax over 75
        float m = fmaxf(d[0], fmaxf(d[1], d[2]));
        #pragma unroll
        for (int o = 16; o > 0; o >>= 1) m = fmaxf(m, __shfl_xor_sync(0xffffffffu, m, o));
        float e[3]; float ssum = 0.f;
        #pragma unroll
        for (int c = 0; c < 3; c++) {
            e[c] = (lane + 32 * c < NK) ? __expf(d[c] - m) : 0.f;
            ssum += e[c];
        }
        #pragma unroll
        for (int o = 16; o > 0; o >>= 1) ssum += __shfl_xor_sync(0xffffffffu, ssum, o);
        float rs = 1.f / ssum;

        #pragma unroll
        for (int c = 0; c < 3; c++) {
            int s = lane + 32 * c;
            if (s < NK) { Ps[wid * 80 + s] = e[c]; Ts[wid * 80 + s] = tk[c]; }
        }
        __syncwarp();

        // AV: lane = dim (and dim+32 for lane<16)
        float o0 = 0.f, o1 = 0.f;
        for (int s = 0; s < NK; s++) {
            float p = Ps[wid * 80 + s];
            int tok = Ts[wid * 80 + s];
            const float* vp = Vs + tok * KSTRIDE;
            o0 = fmaf(p, vp[lane], o0);
            if (lane < 16) o1 = fmaf(p, vp[32 + lane], o1);
        }
        int gtok = t * HW + hq * RES + wq;
        float* dst = g_xa + (long long)gtok * DIM + head * DH;
        dst[lane] = o0 * rs;
        if (lane < 16) dst[32 + lane] = o1 * rs;
        __syncwarp();
    }
}

// ---------------- launch ----------------
extern "C" void kernel_launch(void* const* d_in, const int* in_sizes, int n_in,
                              void* d_out, int out_size) {
    const float* x       = (const float*)d_in[0];
    const float* emb     = (const float*)d_in[1];
    const float* w_mod   = (const float*)d_in[2];
    const float* b_mod   = (const float*)d_in[3];
    const float* qn_w    = (const float*)d_in[4];
    const float* qn_b    = (const float*)d_in[5];
    const float* kn_w    = (const float*)d_in[6];
    const float* kn_b    = (const float*)d_in[7];
    const float* W_fused = (const float*)d_in[8];
    const float* b_fused = (const float*)d_in[9];
    const float* W_out   = (const float*)d_in[10];
    const float* W_mlp   = (const float*)d_in[11];
    const float* b_mlp   = (const float*)d_in[12];
    float* out = (float*)d_out;

    float *p_h, *p_fused, *p_xa, *p_attn;
    cudaGetSymbolAddress((void**)&p_h,     g_h);
    cudaGetSymbolAddress((void**)&p_fused, g_fused);
    cudaGetSymbolAddress((void**)&p_xa,    g_xa);
    cudaGetSymbolAddress((void**)&p_attn,  g_attn);

    cudaFuncSetAttribute(tf32gemm<0>, cudaFuncAttributeMaxDynamicSharedMemorySize, GEMM_SMEM);
    cudaFuncSetAttribute(tf32gemm<2>, cudaFuncAttributeMaxDynamicSharedMemorySize, GEMM_SMEM);
    cudaFuncSetAttribute(tf32gemm<3>, cudaFuncAttributeMaxDynamicSharedMemorySize, GEMM_SMEM);
    cudaFuncSetAttribute(nattn_tiled, cudaFuncAttributeMaxDynamicSharedMemorySize, NA_SMEM);

    mod_kernel<<<T_ * 6, 256>>>(emb, w_mod, b_mod);
    ln_mod_kernel<<<THW, 256>>>(x);
    // fused = h @ W_fused + b ; silu on mlp slice
    tf32gemm<2><<<dim3(NF / 128, (THW + 127) / 128), 256, GEMM_SMEM>>>(
        p_h, DIM, W_fused, b_fused, p_fused, NF, THW, NF, DIM, 3 * DIM, nullptr, nullptr);
    qkv_warp<<<(THW * HEADS) / 8, 256>>>(p_fused, qn_w, qn_b, kn_w, kn_b);
    nattn_tiled<<<dim3(9, HEADS), 256, NA_SMEM>>>();
    // attn_out = xa @ W_out
    tf32gemm<0><<<dim3(DIM / 128, (THW + 127) / 128), 256, GEMM_SMEM>>>(
        p_xa, DIM, W_out, nullptr, p_attn, DIM, THW, DIM, DIM, 0, nullptr, nullptr);
    // out = x + attn + silu(mlp) @ W_mlp + b  (transposed store)
    tf32gemm<3><<<dim3(DIM / 128, (THW + 127) / 128), 256, GEMM_SMEM>>>(
        p_fused + 3 * DIM, NF, W_mlp, b_mlp, out, DIM, THW, DIM, MLP, 0, p_attn, x);
}

// round 7
// speedup vs baseline: 4.2037x; 1.3027x over previous
#include <cuda_runtime.h>
#include <cuda_fp16.h>
#include <math.h>
#include <stdint.h>

// ---------------- problem constants ----------------
#define DIM   768
#define HEADS 16
#define DH    48
#define EMB   1024
#define T_    3
#define RES   24
#define HW    (RES*RES)        // 576
#define THW   (T_*HW)          // 1728
#define MLP   (4*DIM)          // 3072
#define NF    (3*DIM + MLP)    // 5376
#define QKVC  (3*DIM)          // 2304
#define KT    3
#define KH    5
#define KW    5
#define NK    (KT*KH*KW)       // 75
#define EPS   1e-5f

// ---------------- scratch ----------------
__device__ float  g_mod [T_ * 2 * DIM];
__device__ __half g_h   [THW * DIM];          // LN+mod, fp16
__device__ float  g_qkv [THW * QKVC];         // qkv slice of fused, fp32
__device__ __half g_mlpH[THW * MLP];          // silu(mlp) fp16
__device__ float  g_q   [HEADS * THW * DH];
__device__ float  g_k   [HEADS * THW * DH];
__device__ float  g_v   [HEADS * THW * DH];
__device__ __half g_xa  [THW * DIM];          // attention out fp16
__device__ float  g_attn[THW * DIM];
// packed fp16 weights: [K/2][N] u32, u32 = half2(W[2k][n], W[2k+1][n])
#define W1OFF 0
#define W2OFF (768/2*5376)                    // 2064384
#define W3OFF (W2OFF + 768/2*768)             // 2359296
__device__ uint32_t g_wH[W3OFF + 3072/2*768];

__device__ __forceinline__ unsigned smem_u32p(const void* p) {
    return (unsigned)__cvta_generic_to_shared(p);
}
__device__ __forceinline__ void mma16(float* c, unsigned a0, unsigned a1, unsigned a2, unsigned a3,
                                      unsigned b0, unsigned b1) {
    asm volatile("mma.sync.aligned.m16n8k16.row.col.f32.f16.f16.f32 "
                 "{%0,%1,%2,%3},{%4,%5,%6,%7},{%8,%9},{%0,%1,%2,%3};"
                 : "+f"(c[0]), "+f"(c[1]), "+f"(c[2]), "+f"(c[3])
                 : "r"(a0), "r"(a1), "r"(a2), "r"(a3), "r"(b0), "r"(b1));
}

// ---------------- weight pack: out[k2*N+n] = half2(W[2k2][n], W[2k2+1][n]) ----------------
__global__ void packW(const float* __restrict__ W, uint32_t* __restrict__ out, int K, int N) {
    int idx = blockIdx.x * 256 + threadIdx.x;
    if (idx >= (K / 2) * N) return;
    int k2 = idx / N, n = idx - k2 * N;
    unsigned lo = __half_as_ushort(__float2half_rn(W[(long long)(2 * k2) * N + n]));
    unsigned hi = __half_as_ushort(__float2half_rn(W[(long long)(2 * k2 + 1) * N + n]));
    out[idx] = (hi << 16) | lo;
}

// ---------------- K1: mod = silu(emb) @ w_mod + b_mod ----------------
__global__ void mod_kernel(const float* __restrict__ emb,
                           const float* __restrict__ w_mod,
                           const float* __restrict__ b_mod) {
    int t = blockIdx.x / 6;
    int n = (blockIdx.x % 6) * 256 + threadIdx.x;
    __shared__ float se[EMB];
    for (int i = threadIdx.x; i < EMB; i += 256) {
        float e = emb[t * EMB + i];
        se[i] = e / (1.f + __expf(-e));
    }
    __syncthreads();
    float acc = b_mod[n];
    for (int e = 0; e < EMB; e++)
        acc += se[e] * w_mod[e * (2 * DIM) + n];
    g_mod[t * (2 * DIM) + n] = acc;
}

// ---------------- K2: per-token LN + modulate -> fp16 ----------------
__global__ void ln_mod_kernel(const float* __restrict__ x) {
    int token = blockIdx.x;
    int t  = token / HW;
    int hw = token % HW;
    int tid = threadIdx.x;
    __shared__ float red[256];

    float v[3];
    float sum = 0.f;
    #pragma unroll
    for (int i = 0; i < 3; i++) {
        int d = tid + i * 256;
        v[i] = x[((t * DIM) + d) * HW + hw];
        sum += v[i];
    }
    red[tid] = sum; __syncthreads();
    for (int s = 128; s > 0; s >>= 1) { if (tid < s) red[tid] += red[tid + s]; __syncthreads(); }
    float mean = red[0] * (1.f / DIM);
    __syncthreads();

    float sq = 0.f;
    #pragma unroll
    for (int i = 0; i < 3; i++) { float d = v[i] - mean; sq += d * d; }
    red[tid] = sq; __syncthreads();
    for (int s = 128; s > 0; s >>= 1) { if (tid < s) red[tid] += red[tid + s]; __syncthreads(); }
    float var = red[0] * (1.f / DIM);
    float rstd = rsqrtf(var + EPS);

    #pragma unroll
    for (int i = 0; i < 3; i++) {
        int d = tid + i * 256;
        float y = (v[i] - mean) * rstd;
        float scale = g_mod[t * (2 * DIM) + d];
        float shift = g_mod[t * (2 * DIM) + DIM + d];
        g_h[token * DIM + d] = __float2half_rn(y * (1.f + scale) + shift);
    }
}

// ---------------- fp16 tensor GEMM: C[M,N] = A[M,K]fp16 @ Wpacked ----------------
// MODE 0: plain fp32 out
// MODE 2: GEMM1: col<2304 -> +bias fp32 to C(ldc=2304); col>=2304 -> +bias, silu, fp16 to g_mlpH
// MODE 3: out[(t*DIM+col)*HW+hw] = acc + bias[col] + attn[r*DIM+col] + xres[...]
#define GS 3
#define A_STG_U32 (128*20)                 // 80B per row
#define B_STG_U32 (16*136)                 // 544B per row
#define STG_U32   (A_STG_U32 + B_STG_U32)  // 18944 B
#define GEMM_SMEM (GS*STG_U32*4)

template<int MODE>
__global__ void __launch_bounds__(256)
hgemm(const __half* __restrict__ A, int lda,
      const uint32_t* __restrict__ Bp, int N,
      const float* __restrict__ bias,
      float* __restrict__ C, int ldc,
      int M, int K,
      const float* __restrict__ attn, const float* __restrict__ xres)
{
    extern __shared__ uint32_t smu[];

    const int tid  = threadIdx.x;
    const int lane = tid & 31;
    const int wid  = tid >> 5;
    const int wm   = wid & 3;
    const int wn   = wid >> 2;
    const int lr   = lane >> 2;
    const int lc   = lane & 3;
    const int m0   = blockIdx.y * 128;
    const int n0   = blockIdx.x * 128;

    float acc[2][8][4];
    #pragma unroll
    for (int i = 0; i < 2; i++)
        #pragma unroll
        for (int j = 0; j < 8; j++)
            #pragma unroll
            for (int q = 0; q < 4; q++) acc[i][j][q] = 0.f;

    const int kTiles = K / 32;

    auto load_stage = [&](int kt, int st) {
        int k0 = kt * 32;
        uint32_t abase = smem_u32p(smu + st * STG_U32);
        uint32_t bbase = abase + A_STG_U32 * 4;
        #pragma unroll
        for (int r = 0; r < 2; r++) {
            int idx = tid + 256 * r;           // 0..511
            int m = idx >> 2, c = idx & 3;
            const __half* src = A + (long long)(m0 + m) * lda + k0 + c * 8;
            uint32_t dst = abase + m * 80 + c * 16;
            int sz = (m0 + m < M) ? 16 : 0;
            asm volatile("cp.async.cg.shared.global [%0],[%1],16,%2;\n" :: "r"(dst), "l"(src), "r"(sz));
        }
        #pragma unroll
        for (int r = 0; r < 2; r++) {
            int idx = tid + 256 * r;
            int k2 = idx >> 5, c = idx & 31;
            const uint32_t* src = Bp + (long long)(kt * 16 + k2) * N + n0 + c * 4;
            uint32_t dst = bbase + k2 * 544 + c * 16;
            asm volatile("cp.async.cg.shared.global [%0],[%1],16,16;\n" :: "r"(dst), "l"(src));
        }
        asm volatile("cp.async.commit_group;\n");
    };

    #pragma unroll
    for (int s = 0; s < GS - 1; s++) load_stage(s, s);

    for (int kt = 0; kt < kTiles; kt++) {
        if (kt + GS - 1 < kTiles) load_stage(kt + GS - 1, (kt + GS - 1) % GS);
        else asm volatile("cp.async.commit_group;\n");

        asm volatile("cp.async.wait_group %0;\n" :: "n"(GS - 2));
        __syncthreads();

        const uint32_t* AsU = smu + (kt % GS) * STG_U32;
        const uint32_t* BsU = AsU + A_STG_U32;

        #pragma unroll
        for (int ks = 0; ks < 2; ks++) {
            unsigned af[2][4];
            #pragma unroll
            for (int i = 0; i < 2; i++) {
                int row = wm * 32 + i * 16 + lr;
                af[i][0] = AsU[row * 20 + ks * 8 + lc];
                af[i][1] = AsU[(row + 8) * 20 + ks * 8 + lc];
                af[i][2] = AsU[row * 20 + ks * 8 + 4 + lc];
                af[i][3] = AsU[(row + 8) * 20 + ks * 8 + 4 + lc];
            }
            #pragma unroll
            for (int j = 0; j < 8; j++) {
                int colw = wn * 64 + j * 8 + lr;
                unsigned b0 = BsU[(ks * 8 + lc) * 136 + colw];
                unsigned b1 = BsU[(ks * 8 + 4 + lc) * 136 + colw];
                mma16(acc[0][j], af[0][0], af[0][1], af[0][2], af[0][3], b0, b1);
                mma16(acc[1][j], af[1][0], af[1][1], af[1][2], af[1][3], b0, b1);
            }
        }
        __syncthreads();
    }

    // epilogue
    #pragma unroll
    for (int i = 0; i < 2; i++) {
        #pragma unroll
        for (int j = 0; j < 8; j++) {
            int col = n0 + wn * 64 + j * 8 + 2 * lc;
            #pragma unroll
            for (int h = 0; h < 2; h++) {
                int r = m0 + wm * 32 + i * 16 + lr + h * 8;
                if (r >= M) continue;
                float v0 = acc[i][j][h * 2 + 0];
                float v1 = acc[i][j][h * 2 + 1];
                if (MODE == 0) {
                    *(float2*)(C + (long long)r * ldc + col) = make_float2(v0, v1);
                } else if (MODE == 2) {
                    v0 += bias[col]; v1 += bias[col + 1];
                    if (col < QKVC) {
                        *(float2*)(C + (long long)r * QKVC + col) = make_float2(v0, v1);
                    } else {
                        v0 = v0 / (1.f + __expf(-v0));
                        v1 = v1 / (1.f + __expf(-v1));
                        *(__half2*)(g_mlpH + (long long)r * MLP + col - QKVC) = __floats2half2_rn(v0, v1);
                    }
                } else { // MODE 3
                    int t = r / HW, hw = r % HW;
                    long long o0 = ((long long)t * DIM + col) * HW + hw;
                    long long o1 = o0 + HW;
                    C[o0] = v0 + bias[col]     + attn[(long long)r * DIM + col]     + xres[o0];
                    C[o1] = v1 + bias[col + 1] + attn[(long long)r * DIM + col + 1] + xres[o1];
                }
            }
        }
    }
}

// ---------------- K4: warp-per-(token,head) QK-norm + RoPE, V copy ----------------
__global__ void qkv_warp(const float* __restrict__ fused,
                         const float* __restrict__ qn_w, const float* __restrict__ qn_b,
                         const float* __restrict__ kn_w, const float* __restrict__ kn_b) {
    int wid  = threadIdx.x >> 5;
    int lane = threadIdx.x & 31;
    int gw = blockIdx.x * 8 + wid;
    int token = gw >> 4;
    int head  = gw & 15;
    int t  = token / HW;
    int hh = (token / RES) % RES;
    int ww = token % RES;

    __shared__ float s_all[8][DH];
    float* s = s_all[wid];

    const float* base = fused + (long long)token * QKVC + head * DH;

    {
        float v0 = base[2 * DIM + lane];
        g_v[((long long)head * THW + token) * DH + lane] = v0;
        if (lane < 16)
            g_v[((long long)head * THW + token) * DH + 32 + lane] = base[2 * DIM + 32 + lane];
    }

    #pragma unroll
    for (int which = 0; which < 2; which++) {
        const float* w  = which ? kn_w : qn_w;
        const float* bb = which ? kn_b : qn_b;
        float v0 = base[which * DIM + lane];
        float v1 = (lane < 16) ? base[which * DIM + 32 + lane] : 0.f;

        float sum = v0 + v1;
        #pragma unroll
        for (int o = 16; o > 0; o >>= 1) sum += __shfl_xor_sync(0xffffffffu, sum, o);
        float mean = sum * (1.f / DH);

        float d0 = v0 - mean;
        float d1 = (lane < 16) ? (v1 - mean) : 0.f;
        float sq = d0 * d0 + d1 * d1;
        #pragma unroll
        for (int o = 16; o > 0; o >>= 1) sq += __shfl_xor_sync(0xffffffffu, sq, o);
        float rstd = rsqrtf(sq * (1.f / DH) + EPS);

        s[lane] = d0 * rstd * w[lane] + bb[lane];
        if (lane < 16)
            s[32 + lane] = d1 * rstd * w[32 + lane] + bb[32 + lane];
        __syncwarp();

        if (lane < DH / 2) {
            int i = lane;
            float x1 = s[2 * i], x2 = s[2 * i + 1];
            float pos = (i < 8) ? (float)t : (i < 16) ? (float)hh : (float)ww;
            int j = i & 7;
            float inv = powf(10000.f, -(float)j * 0.125f);
            float ang = pos * inv;
            float sn, cs;
            sincosf(ang, &sn, &cs);
            float o1 = x1 * cs - x2 * sn;
            float o2 = x1 * sn + x2 * cs;
            float sc = which ? 1.f : 0.14433756729740643f;
            float* dst = (which ? g_k : g_q) + ((long long)head * THW + token) * DH;
            dst[2 * i]     = o1 * sc;
            dst[2 * i + 1] = o2 * sc;
        }
        __syncwarp();
    }
}

// ---------------- K5: tiled neighborhood attention -> fp16 xa ----------------
#define UTOK 432
#define KSTRIDE 50
#define NA_SMEM ((2*UTOK*KSTRIDE + 192*DH + 8*80) * 4 + 8*80*4)

__global__ void __launch_bounds__(256)
nattn_tiled() {
    extern __shared__ float sm[];
    float* Ks = sm;
    float* Vs = Ks + UTOK * KSTRIDE;
    float* Qs = Vs + UTOK * KSTRIDE;
    float* Ps = Qs + 192 * DH;
    int*   Ts = (int*)(Ps + 8 * 80);

    const int tile = blockIdx.x;
    const int head = blockIdx.y;
    const int th0 = (tile / 3) * 8;
    const int tw0 = (tile % 3) * 8;
    const int kh0 = min(max(th0 - 2, 0), RES - 12);
    const int kw0 = min(max(tw0 - 2, 0), RES - 12);
    const int tid  = threadIdx.x;
    const int wid  = tid >> 5;
    const int lane = tid & 31;

    const float* kbase = g_k + (long long)head * THW * DH;
    const float* vbase = g_v + (long long)head * THW * DH;
    const float* qbase = g_q + (long long)head * THW * DH;

    for (int i = tid; i < UTOK * 24; i += 256) {
        int tok = i / 24, u = i % 24;
        int kt = tok / 144, rem = tok % 144;
        int rr = rem / 12, cc = rem % 12;
        int gtok = kt * HW + (kh0 + rr) * RES + (kw0 + cc);
        float2 kv = *(const float2*)(kbase + (long long)gtok * DH + 2 * u);
        float2 vv = *(const float2*)(vbase + (long long)gtok * DH + 2 * u);
        *(float2*)&Ks[tok * KSTRIDE + 2 * u] = kv;
        *(float2*)&Vs[tok * KSTRIDE + 2 * u] = vv;
    }
    for (int i = tid; i < 192 * 24; i += 256) {
        int qi = i / 24, u = i % 24;
        int t = qi / 64, rem = qi % 64;
        int qr = rem / 8, qc = rem % 8;
        int gtok = t * HW + (th0 + qr) * RES + (tw0 + qc);
        *(float2*)&Qs[qi * DH + 2 * u] = *(const float2*)(qbase + (long long)gtok * DH + 2 * u);
    }
    __syncthreads();

    for (int it = 0; it < 24; it++) {
        int qi = wid * 24 + it;
        int t = qi / 64, rem = qi % 64;
        int qr = rem / 8, qc = rem % 8;
        int hq = th0 + qr, wq = tw0 + qc;
        int rb = min(max(hq - 2, 0), RES - KH) - kh0;
        int cb = min(max(wq - 2, 0), RES - KW) - kw0;
        const float* qs = Qs + qi * DH;

        float d[3] = {-1e30f, -1e30f, -1e30f};
        int   tk[3] = {0, 0, 0};
        #pragma unroll
        for (int c = 0; c < 3; c++) {
            int s = lane + 32 * c;
            if (s < NK) {
                int kt = s / 25, r2 = (s % 25) / 5, c2 = s % 5;
                int tok = kt * 144 + (rb + r2) * 12 + (cb + c2);
                tk[c] = tok;
                const float* kp = Ks + tok * KSTRIDE;
                float acc = 0.f;
                #pragma unroll
                for (int u = 0; u < 24; u++) {
                    float2 qv = *(const float2*)(qs + 2 * u);
                    float2 kv = *(const float2*)(kp + 2 * u);
                    acc = fmaf(qv.x, kv.x, acc);
                    acc = fmaf(qv.y, kv.y, acc);
                }
                d[c] = acc;
            }
        }
        float m = fmaxf(d[0], fmaxf(d[1], d[2]));
        #pragma unroll
        for (int o = 16; o > 0; o >>= 1) m = fmaxf(m, __shfl_xor_sync(0xffffffffu, m, o));
        float e[3]; float ssum = 0.f;
        #pragma unroll
        for (int c = 0; c < 3; c++) {
            e[c] = (lane + 32 * c < NK) ? __expf(d[c] - m) : 0.f;
            ssum += e[c];
        }
        #pragma unroll
        for (int o = 16; o > 0; o >>= 1) ssum += __shfl_xor_sync(0xffffffffu, ssum, o);
        float rs = 1.f / ssum;

        #pragma unroll
        for (int c = 0; c < 3; c++) {
            int s = lane + 32 * c;
            if (s < NK) { Ps[wid * 80 + s] = e[c]; Ts[wid * 80 + s] = tk[c]; }
        }
        __syncwarp();

        float o0 = 0.f, o1 = 0.f;
        for (int s = 0; s < NK; s++) {
            float p = Ps[wid * 80 + s];
            int tok = Ts[wid * 80 + s];
            const float* vp = Vs + tok * KSTRIDE;
            o0 = fmaf(p, vp[lane], o0);
            if (lane < 16) o1 = fmaf(p, vp[32 + lane], o1);
        }
        int gtok = t * HW + hq * RES + wq;
        __half* dst = g_xa + (long long)gtok * DIM + head * DH;
        dst[lane] = __float2half_rn(o0 * rs);
        if (lane < 16) dst[32 + lane] = __float2half_rn(o1 * rs);
        __syncwarp();
    }
}

// ---------------- launch ----------------
extern "C" void kernel_launch(void* const* d_in, const int* in_sizes, int n_in,
                              void* d_out, int out_size) {
    const float* x       = (const float*)d_in[0];
    const float* emb     = (const float*)d_in[1];
    const float* w_mod   = (const float*)d_in[2];
    const float* b_mod   = (const float*)d_in[3];
    const float* qn_w    = (const float*)d_in[4];
    const float* qn_b    = (const float*)d_in[5];
    const float* kn_w    = (const float*)d_in[6];
    const float* kn_b    = (const float*)d_in[7];
    const float* W_fused = (const float*)d_in[8];
    const float* b_fused = (const float*)d_in[9];
    const float* W_out   = (const float*)d_in[10];
    const float* W_mlp   = (const float*)d_in[11];
    const float* b_mlp   = (const float*)d_in[12];
    float* out = (float*)d_out;

    __half *p_h, *p_mlpH, *p_xa;
    float *p_qkv, *p_attn;
    uint32_t* p_wH;
    cudaGetSymbolAddress((void**)&p_h,    g_h);
    cudaGetSymbolAddress((void**)&p_qkv,  g_qkv);
    cudaGetSymbolAddress((void**)&p_mlpH, g_mlpH);
    cudaGetSymbolAddress((void**)&p_xa,   g_xa);
    cudaGetSymbolAddress((void**)&p_attn, g_attn);
    cudaGetSymbolAddress((void**)&p_wH,   g_wH);

    cudaFuncSetAttribute(hgemm<0>, cudaFuncAttributeMaxDynamicSharedMemorySize, GEMM_SMEM);
    cudaFuncSetAttribute(hgemm<2>, cudaFuncAttributeMaxDynamicSharedMemorySize, GEMM_SMEM);
    cudaFuncSetAttribute(hgemm<3>, cudaFuncAttributeMaxDynamicSharedMemorySize, GEMM_SMEM);
    cudaFuncSetAttribute(nattn_tiled, cudaFuncAttributeMaxDynamicSharedMemorySize, NA_SMEM);

    // pack weights to fp16 (k-pair interleaved)
    packW<<<(768/2*5376 + 255)/256, 256>>>(W_fused, p_wH + W1OFF, 768, 5376);
    packW<<<(768/2*768  + 255)/256, 256>>>(W_out,   p_wH + W2OFF, 768, 768);
    packW<<<(3072/2*768 + 255)/256, 256>>>(W_mlp,   p_wH + W3OFF, 3072, 768);

    mod_kernel<<<T_ * 6, 256>>>(emb, w_mod, b_mod);
    ln_mod_kernel<<<THW, 256>>>(x);

    // GEMM1: fused; qkv slice fp32 -> g_qkv, mlp slice silu fp16 -> g_mlpH
    hgemm<2><<<dim3(NF / 128, 14), 256, GEMM_SMEM>>>(
        p_h, DIM, p_wH + W1OFF, NF, b_fused, p_qkv, QKVC, THW, DIM, nullptr, nullptr);
    qkv_warp<<<(THW * HEADS) / 8, 256>>>(p_qkv, qn_w, qn_b, kn_w, kn_b);
    nattn_tiled<<<dim3(9, HEADS), 256, NA_SMEM>>>();
    // GEMM2: attn = xa @ W_out
    hgemm<0><<<dim3(DIM / 128, 14), 256, GEMM_SMEM>>>(
        p_xa, DIM, p_wH + W2OFF, DIM, nullptr, p_attn, DIM, THW, DIM, nullptr, nullptr);
    // GEMM3: out = x + attn + silu(mlp) @ W_mlp + b_mlp (transposed store)
    hgemm<3><<<dim3(DIM / 128, 14), 256, GEMM_SMEM>>>(
        p_mlpH, MLP, p_wH + W3OFF, DIM, b_mlp, out, DIM, THW, MLP, p_attn, x);
}

// round 8
// speedup vs baseline: 4.7241x; 1.1238x over previous
#include <cuda_runtime.h>
#include <cuda_fp16.h>
#include <math.h>
#include <stdint.h>

// ---------------- problem constants ----------------
#define DIM   768
#define HEADS 16
#define DH    48
#define EMB   1024
#define T_    3
#define RES   24
#define HW    (RES*RES)        // 576
#define THW   (T_*HW)          // 1728
#define MLP   (4*DIM)          // 3072
#define NF    (3*DIM + MLP)    // 5376
#define QKVC  (3*DIM)          // 2304
#define KT    3
#define KH    5
#define KW    5
#define NK    (KT*KH*KW)       // 75
#define EPS   1e-5f

// ---------------- scratch ----------------
__device__ float  g_mod  [T_ * 2 * DIM];
__device__ float  g_modp [8][T_ * 2 * DIM];   // split-k partials
__device__ __half g_h    [THW * DIM];
__device__ float  g_qkv  [THW * QKVC];
__device__ __half g_mlpH [THW * MLP];
__device__ float  g_q    [HEADS * THW * DH];
__device__ float  g_k    [HEADS * THW * DH];
__device__ float  g_v    [HEADS * THW * DH];
__device__ __half g_xa   [THW * DIM];
__device__ float  g_attn [THW * DIM];
// packed fp16 weights: [K/2][N] u32, u32 = half2(W[2k][n], W[2k+1][n])
#define W1OFF 0
#define W2OFF (768/2*5376)
#define W3OFF (W2OFF + 768/2*768)
__device__ uint32_t g_wH[W3OFF + 3072/2*768];

__device__ __forceinline__ unsigned smem_u32p(const void* p) {
    return (unsigned)__cvta_generic_to_shared(p);
}
__device__ __forceinline__ void mma16(float* c, unsigned a0, unsigned a1, unsigned a2, unsigned a3,
                                      unsigned b0, unsigned b1) {
    asm volatile("mma.sync.aligned.m16n8k16.row.col.f32.f16.f16.f32 "
                 "{%0,%1,%2,%3},{%4,%5,%6,%7},{%8,%9},{%0,%1,%2,%3};"
                 : "+f"(c[0]), "+f"(c[1]), "+f"(c[2]), "+f"(c[3])
                 : "r"(a0), "r"(a1), "r"(a2), "r"(a3), "r"(b0), "r"(b1));
}

// ---------------- weight pack ----------------
__global__ void packW(const float* __restrict__ W, uint32_t* __restrict__ out, int K, int N) {
    int idx = blockIdx.x * 256 + threadIdx.x;
    if (idx >= (K / 2) * N) return;
    int k2 = idx / N, n = idx - k2 * N;
    unsigned lo = __half_as_ushort(__float2half_rn(W[(long long)(2 * k2) * N + n]));
    unsigned hi = __half_as_ushort(__float2half_rn(W[(long long)(2 * k2 + 1) * N + n]));
    out[idx] = (hi << 16) | lo;
}

// ---------------- K1: mod = silu(emb) @ w_mod + b_mod  (split-K) ----------------
// grid (3*6, 8): blockIdx.x = t*6 + nchunk ; blockIdx.y = kchunk (128 k each)
__global__ void mod_partial(const float* __restrict__ emb,
                            const float* __restrict__ w_mod) {
    int t  = blockIdx.x / 6;
    int n  = (blockIdx.x % 6) * 256 + threadIdx.x;
    int k0 = blockIdx.y * 128;
    __shared__ float se[128];
    if (threadIdx.x < 128) {
        float e = emb[t * EMB + k0 + threadIdx.x];
        se[threadIdx.x] = e / (1.f + __expf(-e));
    }
    __syncthreads();
    float acc = 0.f;
    #pragma unroll 8
    for (int e = 0; e < 128; e++)
        acc += se[e] * w_mod[(long long)(k0 + e) * (2 * DIM) + n];
    g_modp[blockIdx.y][t * (2 * DIM) + n] = acc;
}
__global__ void mod_reduce(const float* __restrict__ b_mod) {
    int idx = blockIdx.x * 256 + threadIdx.x;      // over 3*1536
    int n = idx % (2 * DIM);
    float acc = b_mod[n];
    #pragma unroll
    for (int c = 0; c < 8; c++) acc += g_modp[c][idx];
    g_mod[idx] = acc;
}

// ---------------- K2: per-token LN + modulate -> fp16 ----------------
__global__ void ln_mod_kernel(const float* __restrict__ x) {
    int token = blockIdx.x;
    int t  = token / HW;
    int hw = token % HW;
    int tid = threadIdx.x;
    __shared__ float red[256];

    float v[3];
    float sum = 0.f;
    #pragma unroll
    for (int i = 0; i < 3; i++) {
        int d = tid + i * 256;
        v[i] = x[((t * DIM) + d) * HW + hw];
        sum += v[i];
    }
    red[tid] = sum; __syncthreads();
    for (int s = 128; s > 0; s >>= 1) { if (tid < s) red[tid] += red[tid + s]; __syncthreads(); }
    float mean = red[0] * (1.f / DIM);
    __syncthreads();

    float sq = 0.f;
    #pragma unroll
    for (int i = 0; i < 3; i++) { float d = v[i] - mean; sq += d * d; }
    red[tid] = sq; __syncthreads();
    for (int s = 128; s > 0; s >>= 1) { if (tid < s) red[tid] += red[tid + s]; __syncthreads(); }
    float var = red[0] * (1.f / DIM);
    float rstd = rsqrtf(var + EPS);

    #pragma unroll
    for (int i = 0; i < 3; i++) {
        int d = tid + i * 256;
        float y = (v[i] - mean) * rstd;
        float scale = g_mod[t * (2 * DIM) + d];
        float shift = g_mod[t * (2 * DIM) + DIM + d];
        g_h[token * DIM + d] = __float2half_rn(y * (1.f + scale) + shift);
    }
}

// ---------------- fp16 tensor GEMM ----------------
#define GS 3
#define A_STG_U32 (128*20)
#define B_STG_U32 (16*136)
#define STG_U32   (A_STG_U32 + B_STG_U32)
#define GEMM_SMEM (GS*STG_U32*4)

template<int MODE>
__global__ void __launch_bounds__(256)
hgemm(const __half* __restrict__ A, int lda,
      const uint32_t* __restrict__ Bp, int N,
      const float* __restrict__ bias,
      float* __restrict__ C, int ldc,
      int M, int K,
      const float* __restrict__ attn, const float* __restrict__ xres)
{
    extern __shared__ uint32_t smu[];

    const int tid  = threadIdx.x;
    const int lane = tid & 31;
    const int wid  = tid >> 5;
    const int wm   = wid & 3;
    const int wn   = wid >> 2;
    const int lr   = lane >> 2;
    const int lc   = lane & 3;
    const int m0   = blockIdx.y * 128;
    const int n0   = blockIdx.x * 128;

    float acc[2][8][4];
    #pragma unroll
    for (int i = 0; i < 2; i++)
        #pragma unroll
        for (int j = 0; j < 8; j++)
            #pragma unroll
            for (int q = 0; q < 4; q++) acc[i][j][q] = 0.f;

    const int kTiles = K / 32;

    auto load_stage = [&](int kt, int st) {
        int k0 = kt * 32;
        uint32_t abase = smem_u32p(smu + st * STG_U32);
        uint32_t bbase = abase + A_STG_U32 * 4;
        #pragma unroll
        for (int r = 0; r < 2; r++) {
            int idx = tid + 256 * r;
            int m = idx >> 2, c = idx & 3;
            const __half* src = A + (long long)(m0 + m) * lda + k0 + c * 8;
            uint32_t dst = abase + m * 80 + c * 16;
            int sz = (m0 + m < M) ? 16 : 0;
            asm volatile("cp.async.cg.shared.global [%0],[%1],16,%2;\n" :: "r"(dst), "l"(src), "r"(sz));
        }
        #pragma unroll
        for (int r = 0; r < 2; r++) {
            int idx = tid + 256 * r;
            int k2 = idx >> 5, c = idx & 31;
            const uint32_t* src = Bp + (long long)(kt * 16 + k2) * N + n0 + c * 4;
            uint32_t dst = bbase + k2 * 544 + c * 16;
            asm volatile("cp.async.cg.shared.global [%0],[%1],16,16;\n" :: "r"(dst), "l"(src));
        }
        asm volatile("cp.async.commit_group;\n");
    };

    #pragma unroll
    for (int s = 0; s < GS - 1; s++) load_stage(s, s);

    for (int kt = 0; kt < kTiles; kt++) {
        if (kt + GS - 1 < kTiles) load_stage(kt + GS - 1, (kt + GS - 1) % GS);
        else asm volatile("cp.async.commit_group;\n");

        asm volatile("cp.async.wait_group %0;\n" :: "n"(GS - 2));
        __syncthreads();

        const uint32_t* AsU = smu + (kt % GS) * STG_U32;
        const uint32_t* BsU = AsU + A_STG_U32;

        #pragma unroll
        for (int ks = 0; ks < 2; ks++) {
            unsigned af[2][4];
            #pragma unroll
            for (int i = 0; i < 2; i++) {
                int row = wm * 32 + i * 16 + lr;
                af[i][0] = AsU[row * 20 + ks * 8 + lc];
                af[i][1] = AsU[(row + 8) * 20 + ks * 8 + lc];
                af[i][2] = AsU[row * 20 + ks * 8 + 4 + lc];
                af[i][3] = AsU[(row + 8) * 20 + ks * 8 + 4 + lc];
            }
            #pragma unroll
            for (int j = 0; j < 8; j++) {
                int colw = wn * 64 + j * 8 + lr;
                unsigned b0 = BsU[(ks * 8 + lc) * 136 + colw];
                unsigned b1 = BsU[(ks * 8 + 4 + lc) * 136 + colw];
                mma16(acc[0][j], af[0][0], af[0][1], af[0][2], af[0][3], b0, b1);
                mma16(acc[1][j], af[1][0], af[1][1], af[1][2], af[1][3], b0, b1);
            }
        }
        __syncthreads();
    }

    // epilogue
    #pragma unroll
    for (int i = 0; i < 2; i++) {
        #pragma unroll
        for (int j = 0; j < 8; j++) {
            int col = n0 + wn * 64 + j * 8 + 2 * lc;
            #pragma unroll
            for (int h = 0; h < 2; h++) {
                int r = m0 + wm * 32 + i * 16 + lr + h * 8;
                if (r >= M) continue;
                float v0 = acc[i][j][h * 2 + 0];
                float v1 = acc[i][j][h * 2 + 1];
                if (MODE == 0) {
                    *(float2*)(C + (long long)r * ldc + col) = make_float2(v0, v1);
                } else if (MODE == 2) {
                    v0 += bias[col]; v1 += bias[col + 1];
                    if (col < QKVC) {
                        *(float2*)(C + (long long)r * QKVC + col) = make_float2(v0, v1);
                    } else {
                        v0 = v0 / (1.f + __expf(-v0));
                        v1 = v1 / (1.f + __expf(-v1));
                        *(__half2*)(g_mlpH + (long long)r * MLP + col - QKVC) = __floats2half2_rn(v0, v1);
                    }
                } else { // MODE 3
                    int t = r / HW, hw = r % HW;
                    long long o0 = ((long long)t * DIM + col) * HW + hw;
                    long long o1 = o0 + HW;
                    C[o0] = v0 + bias[col]     + attn[(long long)r * DIM + col]     + xres[o0];
                    C[o1] = v1 + bias[col + 1] + attn[(long long)r * DIM + col + 1] + xres[o1];
                }
            }
        }
    }
}

// ---------------- K4: warp-per-(token,head) QK-norm + RoPE, V copy ----------------
__global__ void qkv_warp(const float* __restrict__ fused,
                         const float* __restrict__ qn_w, const float* __restrict__ qn_b,
                         const float* __restrict__ kn_w, const float* __restrict__ kn_b) {
    int wid  = threadIdx.x >> 5;
    int lane = threadIdx.x & 31;
    int gw = blockIdx.x * 8 + wid;
    int token = gw >> 4;
    int head  = gw & 15;
    int t  = token / HW;
    int hh = (token / RES) % RES;
    int ww = token % RES;

    __shared__ float s_all[8][DH];
    float* s = s_all[wid];

    const float* base = fused + (long long)token * QKVC + head * DH;

    {
        float v0 = base[2 * DIM + lane];
        g_v[((long long)head * THW + token) * DH + lane] = v0;
        if (lane < 16)
            g_v[((long long)head * THW + token) * DH + 32 + lane] = base[2 * DIM + 32 + lane];
    }

    #pragma unroll
    for (int which = 0; which < 2; which++) {
        const float* w  = which ? kn_w : qn_w;
        const float* bb = which ? kn_b : qn_b;
        float v0 = base[which * DIM + lane];
        float v1 = (lane < 16) ? base[which * DIM + 32 + lane] : 0.f;

        float sum = v0 + v1;
        #pragma unroll
        for (int o = 16; o > 0; o >>= 1) sum += __shfl_xor_sync(0xffffffffu, sum, o);
        float mean = sum * (1.f / DH);

        float d0 = v0 - mean;
        float d1 = (lane < 16) ? (v1 - mean) : 0.f;
        float sq = d0 * d0 + d1 * d1;
        #pragma unroll
        for (int o = 16; o > 0; o >>= 1) sq += __shfl_xor_sync(0xffffffffu, sq, o);
        float rstd = rsqrtf(sq * (1.f / DH) + EPS);

        s[lane] = d0 * rstd * w[lane] + bb[lane];
        if (lane < 16)
            s[32 + lane] = d1 * rstd * w[32 + lane] + bb[32 + lane];
        __syncwarp();

        if (lane < DH / 2) {
            int i = lane;
            float x1 = s[2 * i], x2 = s[2 * i + 1];
            float pos = (i < 8) ? (float)t : (i < 16) ? (float)hh : (float)ww;
            int j = i & 7;
            float inv = powf(10000.f, -(float)j * 0.125f);
            float ang = pos * inv;
            float sn, cs;
            sincosf(ang, &sn, &cs);
            float o1 = x1 * cs - x2 * sn;
            float o2 = x1 * sn + x2 * cs;
            float sc = which ? 1.f : 0.14433756729740643f;
            float* dst = (which ? g_k : g_q) + ((long long)head * THW + token) * DH;
            dst[2 * i]     = o1 * sc;
            dst[2 * i + 1] = o2 * sc;
        }
        __syncwarp();
    }
}

// ---------------- K5: tiled neighborhood attention -> fp16 xa ----------------
#define UTOK 432
#define KSTRIDE 50
#define NA_SMEM ((2*UTOK*KSTRIDE + 192*DH + 8*80) * 4 + 8*80*4)

__global__ void __launch_bounds__(256)
nattn_tiled() {
    extern __shared__ float sm[];
    float* Ks = sm;
    float* Vs = Ks + UTOK * KSTRIDE;
    float* Qs = Vs + UTOK * KSTRIDE;
    float* Ps = Qs + 192 * DH;
    int*   Ts = (int*)(Ps + 8 * 80);

    const int tile = blockIdx.x;
    const int head = blockIdx.y;
    const int th0 = (tile / 3) * 8;
    const int tw0 = (tile % 3) * 8;
    const int kh0 = min(max(th0 - 2, 0), RES - 12);
    const int kw0 = min(max(tw0 - 2, 0), RES - 12);
    const int tid  = threadIdx.x;
    const int wid  = tid >> 5;
    const int lane = tid & 31;

    const float* kbase = g_k + (long long)head * THW * DH;
    const float* vbase = g_v + (long long)head * THW * DH;
    const float* qbase = g_q + (long long)head * THW * DH;

    for (int i = tid; i < UTOK * 24; i += 256) {
        int tok = i / 24, u = i % 24;
        int kt = tok / 144, rem = tok % 144;
        int rr = rem / 12, cc = rem % 12;
        int gtok = kt * HW + (kh0 + rr) * RES + (kw0 + cc);
        float2 kv = *(const float2*)(kbase + (long long)gtok * DH + 2 * u);
        float2 vv = *(const float2*)(vbase + (long long)gtok * DH + 2 * u);
        *(float2*)&Ks[tok * KSTRIDE + 2 * u] = kv;
        *(float2*)&Vs[tok * KSTRIDE + 2 * u] = vv;
    }
    for (int i = tid; i < 192 * 24; i += 256) {
        int qi = i / 24, u = i % 24;
        int t = qi / 64, rem = qi % 64;
        int qr = rem / 8, qc = rem % 8;
        int gtok = t * HW + (th0 + qr) * RES + (tw0 + qc);
        *(float2*)&Qs[qi * DH + 2 * u] = *(const float2*)(qbase + (long long)gtok * DH + 2 * u);
    }
    __syncthreads();

    for (int it = 0; it < 24; it++) {
        int qi = wid * 24 + it;
        int t = qi / 64, rem = qi % 64;
        int qr = rem / 8, qc = rem % 8;
        int hq = th0 + qr, wq = tw0 + qc;
        int rb = min(max(hq - 2, 0), RES - KH) - kh0;
        int cb = min(max(wq - 2, 0), RES - KW) - kw0;
        const float* qs = Qs + qi * DH;

        float d[3] = {-1e30f, -1e30f, -1e30f};
        int   tk[3] = {0, 0, 0};
        #pragma unroll
        for (int c = 0; c < 3; c++) {
            int s = lane + 32 * c;
            if (s < NK) {
                int kt = s / 25, r2 = (s % 25) / 5, c2 = s % 5;
                int tok = kt * 144 + (rb + r2) * 12 + (cb + c2);
                tk[c] = tok;
                const float* kp = Ks + tok * KSTRIDE;
                float acc = 0.f;
                #pragma unroll
                for (int u = 0; u < 24; u++) {
                    float2 qv = *(const float2*)(qs + 2 * u);
                    float2 kv = *(const float2*)(kp + 2 * u);
                    acc = fmaf(qv.x, kv.x, acc);
                    acc = fmaf(qv.y, kv.y, acc);
                }
                d[c] = acc;
            }
        }
        float m = fmaxf(d[0], fmaxf(d[1], d[2]));
        #pragma unroll
        for (int o = 16; o > 0; o >>= 1) m = fmaxf(m, __shfl_xor_sync(0xffffffffu, m, o));
        float e[3]; float ssum = 0.f;
        #pragma unroll
        for (int c = 0; c < 3; c++) {
            e[c] = (lane + 32 * c < NK) ? __expf(d[c] - m) : 0.f;
            ssum += e[c];
        }
        #pragma unroll
        for (int o = 16; o > 0; o >>= 1) ssum += __shfl_xor_sync(0xffffffffu, ssum, o);
        float rs = 1.f / ssum;

        #pragma unroll
        for (int c = 0; c < 3; c++) {
            int s = lane + 32 * c;
            if (s < NK) { Ps[wid * 80 + s] = e[c]; Ts[wid * 80 + s] = tk[c]; }
        }
        __syncwarp();

        float o0 = 0.f, o1 = 0.f;
        for (int s = 0; s < NK; s++) {
            float p = Ps[wid * 80 + s];
            int tok = Ts[wid * 80 + s];
            const float* vp = Vs + tok * KSTRIDE;
            o0 = fmaf(p, vp[lane], o0);
            if (lane < 16) o1 = fmaf(p, vp[32 + lane], o1);
        }
        int gtok = t * HW + hq * RES + wq;
        __half* dst = g_xa + (long long)gtok * DIM + head * DH;
        dst[lane] = __float2half_rn(o0 * rs);
        if (lane < 16) dst[32 + lane] = __float2half_rn(o1 * rs);
        __syncwarp();
    }
}

// ---------------- launch ----------------
extern "C" void kernel_launch(void* const* d_in, const int* in_sizes, int n_in,
                              void* d_out, int out_size) {
    const float* x       = (const float*)d_in[0];
    const float* emb     = (const float*)d_in[1];
    const float* w_mod   = (const float*)d_in[2];
    const float* b_mod   = (const float*)d_in[3];
    const float* qn_w    = (const float*)d_in[4];
    const float* qn_b    = (const float*)d_in[5];
    const float* kn_w    = (const float*)d_in[6];
    const float* kn_b    = (const float*)d_in[7];
    const float* W_fused = (const float*)d_in[8];
    const float* b_fused = (const float*)d_in[9];
    const float* W_out   = (const float*)d_in[10];
    const float* W_mlp   = (const float*)d_in[11];
    const float* b_mlp   = (const float*)d_in[12];
    float* out = (float*)d_out;

    __half *p_h, *p_mlpH, *p_xa;
    float *p_qkv, *p_attn;
    uint32_t* p_wH;
    cudaGetSymbolAddress((void**)&p_h,    g_h);
    cudaGetSymbolAddress((void**)&p_qkv,  g_qkv);
    cudaGetSymbolAddress((void**)&p_mlpH, g_mlpH);
    cudaGetSymbolAddress((void**)&p_xa,   g_xa);
    cudaGetSymbolAddress((void**)&p_attn, g_attn);
    cudaGetSymbolAddress((void**)&p_wH,   g_wH);

    cudaFuncSetAttribute(hgemm<0>, cudaFuncAttributeMaxDynamicSharedMemorySize, GEMM_SMEM);
    cudaFuncSetAttribute(hgemm<2>, cudaFuncAttributeMaxDynamicSharedMemorySize, GEMM_SMEM);
    cudaFuncSetAttribute(hgemm<3>, cudaFuncAttributeMaxDynamicSharedMemorySize, GEMM_SMEM);
    cudaFuncSetAttribute(nattn_tiled, cudaFuncAttributeMaxDynamicSharedMemorySize, NA_SMEM);

    // pack weights to fp16
    packW<<<(768/2*5376 + 255)/256, 256>>>(W_fused, p_wH + W1OFF, 768, 5376);
    packW<<<(768/2*768  + 255)/256, 256>>>(W_out,   p_wH + W2OFF, 768, 768);
    packW<<<(3072/2*768 + 255)/256, 256>>>(W_mlp,   p_wH + W3OFF, 3072, 768);

    // mod GEMM: split-K (144 CTAs) + deterministic reduce
    mod_partial<<<dim3(T_ * 6, 8), 256>>>(emb, w_mod);
    mod_reduce<<<(T_ * 2 * DIM) / 256, 256>>>(b_mod);

    ln_mod_kernel<<<THW, 256>>>(x);

    // GEMM1: fused; qkv slice fp32 -> g_qkv, mlp slice silu fp16 -> g_mlpH
    hgemm<2><<<dim3(NF / 128, 14), 256, GEMM_SMEM>>>(
        p_h, DIM, p_wH + W1OFF, NF, b_fused, p_qkv, QKVC, THW, DIM, nullptr, nullptr);
    qkv_warp<<<(THW * HEADS) / 8, 256>>>(p_qkv, qn_w, qn_b, kn_w, kn_b);
    nattn_tiled<<<dim3(9, HEADS), 256, NA_SMEM>>>();
    // GEMM2: attn = xa @ W_out
    hgemm<0><<<dim3(DIM / 128, 14), 256, GEMM_SMEM>>>(
        p_xa, DIM, p_wH + W2OFF, DIM, nullptr, p_attn, DIM, THW, DIM, nullptr, nullptr);
    // GEMM3: out = x + attn + silu(mlp) @ W_mlp + b_mlp (transposed store)
    hgemm<3><<<dim3(DIM / 128, 14), 256, GEMM_SMEM>>>(
        p_mlpH, MLP, p_wH + W3OFF, DIM, b_mlp, out, DIM, THW, MLP, p_attn, x);
}

// round 16
// speedup vs baseline: 4.9699x; 1.0520x over previous
#include <cuda_runtime.h>
#include <cuda_fp16.h>
#include <math.h>
#include <stdint.h>

// ---------------- problem constants ----------------
#define DIM   768
#define HEADS 16
#define DH    48
#define EMB   1024
#define T_    3
#define RES   24
#define HW    (RES*RES)        // 576
#define THW   (T_*HW)          // 1728
#define MLP   (4*DIM)          // 3072
#define NF    (3*DIM + MLP)    // 5376
#define QKVC  (3*DIM)          // 2304
#define KT    3
#define KH    5
#define KW    5
#define NK    (KT*KH*KW)       // 75
#define EPS   1e-5f

// ---------------- scratch ----------------
#define KCH 16
__device__ float  g_mod  [T_ * 2 * DIM];
__device__ float  g_modp [KCH][T_ * 2 * DIM];
__device__ __half g_h    [THW * DIM];
__device__ float  g_qkv  [THW * QKVC];
__device__ __half g_mlpH [THW * MLP];
__device__ float  g_q    [HEADS * THW * DH];
__device__ float  g_k    [HEADS * THW * DH];
__device__ float  g_v    [HEADS * THW * DH];
__device__ __half g_xa   [THW * DIM];
__device__ float  g_attn [THW * DIM];
// packed fp16 weights: [K/2][N] u32, u32 = half2(W[2k][n], W[2k+1][n])
#define W1N 5376
#define W1K2 384
#define W2N 768
#define W2K2 384
#define W3N 768
#define W3K2 1536
#define W1OFF 0
#define W2OFF (W1K2*W1N)
#define W3OFF (W2OFF + W2K2*W2N)
#define WTOT  (W3OFF + W3K2*W3N)
__device__ uint32_t g_wH[WTOT];

__device__ __forceinline__ unsigned smem_u32p(const void* p) {
    return (unsigned)__cvta_generic_to_shared(p);
}
__device__ __forceinline__ void mma16(float* c, unsigned a0, unsigned a1, unsigned a2, unsigned a3,
                                      unsigned b0, unsigned b1) {
    asm volatile("mma.sync.aligned.m16n8k16.row.col.f32.f16.f16.f32 "
                 "{%0,%1,%2,%3},{%4,%5,%6,%7},{%8,%9},{%0,%1,%2,%3};"
                 : "+f"(c[0]), "+f"(c[1]), "+f"(c[2]), "+f"(c[3])
                 : "r"(a0), "r"(a1), "r"(a2), "r"(a3), "r"(b0), "r"(b1));
}

// ---------------- weight pack (all 3 matrices, one launch) ----------------
__device__ __forceinline__ uint32_t pack_one(const float* W, int k2, int n, int N) {
    unsigned lo = __half_as_ushort(__float2half_rn(W[(long long)(2 * k2) * N + n]));
    unsigned hi = __half_as_ushort(__float2half_rn(W[(long long)(2 * k2 + 1) * N + n]));
    return (hi << 16) | lo;
}
__global__ void packAll(const float* __restrict__ W1, const float* __restrict__ W2,
                        const float* __restrict__ W3) {
    int idx = blockIdx.x * 256 + threadIdx.x;
    const int n1 = W1K2 * W1N, n2 = W2K2 * W2N, n3 = W3K2 * W3N;
    if (idx < n1) {
        g_wH[W1OFF + idx] = pack_one(W1, idx / W1N, idx % W1N, W1N);
    } else if (idx < n1 + n2) {
        int i = idx - n1;
        g_wH[W2OFF + i] = pack_one(W2, i / W2N, i % W2N, W2N);
    } else if (idx < n1 + n2 + n3) {
        int i = idx - n1 - n2;
        g_wH[W3OFF + i] = pack_one(W3, i / W3N, i % W3N, W3N);
    }
}

// ---------------- K1: mod = silu(emb) @ w_mod + b_mod  (split-K x16) ----------------
__global__ void mod_partial(const float* __restrict__ emb,
                            const float* __restrict__ w_mod) {
    int t  = blockIdx.x / 6;
    int n  = (blockIdx.x % 6) * 256 + threadIdx.x;
    int k0 = blockIdx.y * (EMB / KCH);           // 64 k each
    __shared__ float se[EMB / KCH];
    if (threadIdx.x < EMB / KCH) {
        float e = emb[t * EMB + k0 + threadIdx.x];
        se[threadIdx.x] = e / (1.f + __expf(-e));
    }
    __syncthreads();
    float acc = 0.f;
    #pragma unroll 8
    for (int e = 0; e < EMB / KCH; e++)
        acc += se[e] * w_mod[(long long)(k0 + e) * (2 * DIM) + n];
    g_modp[blockIdx.y][t * (2 * DIM) + n] = acc;
}
__global__ void mod_reduce(const float* __restrict__ b_mod) {
    int idx = blockIdx.x * 256 + threadIdx.x;
    int n = idx % (2 * DIM);
    float acc = b_mod[n];
    #pragma unroll
    for (int c = 0; c < KCH; c++) acc += g_modp[c][idx];
    g_mod[idx] = acc;
}

// ---------------- K2: per-token LN + modulate -> fp16 ----------------
__global__ void ln_mod_kernel(const float* __restrict__ x) {
    int token = blockIdx.x;
    int t  = token / HW;
    int hw = token % HW;
    int tid = threadIdx.x;
    __shared__ float red[256];

    float v[3];
    float sum = 0.f;
    #pragma unroll
    for (int i = 0; i < 3; i++) {
        int d = tid + i * 256;
        v[i] = x[((t * DIM) + d) * HW + hw];
        sum += v[i];
    }
    red[tid] = sum; __syncthreads();
    for (int s = 128; s > 0; s >>= 1) { if (tid < s) red[tid] += red[tid + s]; __syncthreads(); }
    float mean = red[0] * (1.f / DIM);
    __syncthreads();

    float sq = 0.f;
    #pragma unroll
    for (int i = 0; i < 3; i++) { float d = v[i] - mean; sq += d * d; }
    red[tid] = sq; __syncthreads();
    for (int s = 128; s > 0; s >>= 1) { if (tid < s) red[tid] += red[tid + s]; __syncthreads(); }
    float var = red[0] * (1.f / DIM);
    float rstd = rsqrtf(var + EPS);

    #pragma unroll
    for (int i = 0; i < 3; i++) {
        int d = tid + i * 256;
        float y = (v[i] - mean) * rstd;
        float scale = g_mod[t * (2 * DIM) + d];
        float shift = g_mod[t * (2 * DIM) + DIM + d];
        g_h[token * DIM + d] = __float2half_rn(y * (1.f + scale) + shift);
    }
}

// ---------------- fp16 tensor GEMM, templated tile height ----------------
// MODE 0: plain fp32 out
// MODE 2: GEMM1: col<2304 -> +bias fp32 to C(ldc=2304); col>=2304 -> +bias, silu, fp16 to g_mlpH
// MODE 3: out[(t*DIM+col)*HW+hw] = acc + bias[col] + attn[r*DIM+col] + xres[...]
#define GS 3
#define B_STG_U32 (16*136)
#define GEMM_SMEM_BM(BM) (GS * ((BM)*20 + B_STG_U32) * 4)

template<int MODE, int BM>
__global__ void __launch_bounds__(256)
hgemm(const __half* __restrict__ A, int lda,
      const uint32_t* __restrict__ Bp, int N,
      const float* __restrict__ bias,
      float* __restrict__ C, int ldc,
      int M, int K,
      const float* __restrict__ attn, const float* __restrict__ xres)
{
    constexpr int WM = BM / 32;          // warps along M (4 or 2)
    constexpr int WN = 8 / WM;           // warps along N (2 or 4)
    constexpr int NJ = 16 / WN;          // 8x-cols per warp (8 or 4)
    constexpr int A_STG = BM * 20;       // u32 per A stage
    constexpr int STG = A_STG + B_STG_U32;

    extern __shared__ uint32_t smu[];

    const int tid  = threadIdx.x;
    const int lane = tid & 31;
    const int wid  = tid >> 5;
    const int wm   = wid % WM;
    const int wn   = wid / WM;
    const int lr   = lane >> 2;
    const int lc   = lane & 3;
    const int m0   = blockIdx.y * BM;
    const int n0   = blockIdx.x * 128;

    float acc[2][NJ][4];
    #pragma unroll
    for (int i = 0; i < 2; i++)
        #pragma unroll
        for (int j = 0; j < NJ; j++)
            #pragma unroll
            for (int q = 0; q < 4; q++) acc[i][j][q] = 0.f;

    const int kTiles = K / 32;

    auto load_stage = [&](int kt, int st) {
        int k0 = kt * 32;
        uint32_t abase = smem_u32p(smu + st * STG);
        uint32_t bbase = abase + A_STG * 4;
        #pragma unroll
        for (int r = 0; r < BM / 64; r++) {
            int idx = tid + 256 * r;
            int m = idx >> 2, c = idx & 3;
            const __half* src = A + (long long)(m0 + m) * lda + k0 + c * 8;
            uint32_t dst = abase + m * 80 + c * 16;
            int sz = (m0 + m < M) ? 16 : 0;
            asm volatile("cp.async.cg.shared.global [%0],[%1],16,%2;\n" :: "r"(dst), "l"(src), "r"(sz));
        }
        #pragma unroll
        for (int r = 0; r < 2; r++) {
            int idx = tid + 256 * r;
            int k2 = idx >> 5, c = idx & 31;
            const uint32_t* src = Bp + (long long)(kt * 16 + k2) * N + n0 + c * 4;
            uint32_t dst = bbase + k2 * 544 + c * 16;
            asm volatile("cp.async.cg.shared.global [%0],[%1],16,16;\n" :: "r"(dst), "l"(src));
        }
        asm volatile("cp.async.commit_group;\n");
    };

    #pragma unroll
    for (int s = 0; s < GS - 1; s++) load_stage(s, s);

    for (int kt = 0; kt < kTiles; kt++) {
        if (kt + GS - 1 < kTiles) load_stage(kt + GS - 1, (kt + GS - 1) % GS);
        else asm volatile("cp.async.commit_group;\n");

        asm volatile("cp.async.wait_group %0;\n" :: "n"(GS - 2));
        __syncthreads();

        const uint32_t* AsU = smu + (kt % GS) * STG;
        const uint32_t* BsU = AsU + A_STG;

        #pragma unroll
        for (int ks = 0; ks < 2; ks++) {
            unsigned af[2][4];
            #pragma unroll
            for (int i = 0; i < 2; i++) {
                int row = wm * 32 + i * 16 + lr;
                af[i][0] = AsU[row * 20 + ks * 8 + lc];
                af[i][1] = AsU[(row + 8) * 20 + ks * 8 + lc];
                af[i][2] = AsU[row * 20 + ks * 8 + 4 + lc];
                af[i][3] = AsU[(row + 8) * 20 + ks * 8 + 4 + lc];
            }
            #pragma unroll
            for (int j = 0; j < NJ; j++) {
                int colw = wn * (NJ * 8) + j * 8 + lr;
                unsigned b0 = BsU[(ks * 8 + lc) * 136 + colw];
                unsigned b1 = BsU[(ks * 8 + 4 + lc) * 136 + colw];
                mma16(acc[0][j], af[0][0], af[0][1], af[0][2], af[0][3], b0, b1);
                mma16(acc[1][j], af[1][0], af[1][1], af[1][2], af[1][3], b0, b1);
            }
        }
        __syncthreads();
    }

    // epilogue
    #pragma unroll
    for (int i = 0; i < 2; i++) {
        #pragma unroll
        for (int j = 0; j < NJ; j++) {
            int col = n0 + wn * (NJ * 8) + j * 8 + 2 * lc;
            #pragma unroll
            for (int h = 0; h < 2; h++) {
                int r = m0 + wm * 32 + i * 16 + lr + h * 8;
                if (r >= M) continue;
                float v0 = acc[i][j][h * 2 + 0];
                float v1 = acc[i][j][h * 2 + 1];
                if (MODE == 0) {
                    *(float2*)(C + (long long)r * ldc + col) = make_float2(v0, v1);
                } else if (MODE == 2) {
                    v0 += bias[col]; v1 += bias[col + 1];
                    if (col < QKVC) {
                        *(float2*)(C + (long long)r * QKVC + col) = make_float2(v0, v1);
                    } else {
                        v0 = v0 / (1.f + __expf(-v0));
                        v1 = v1 / (1.f + __expf(-v1));
                        *(__half2*)(g_mlpH + (long long)r * MLP + col - QKVC) = __floats2half2_rn(v0, v1);
                    }
                } else { // MODE 3
                    int t = r / HW, hw = r % HW;
                    long long o0 = ((long long)t * DIM + col) * HW + hw;
                    long long o1 = o0 + HW;
                    C[o0] = v0 + bias[col]     + attn[(long long)r * DIM + col]     + xres[o0];
                    C[o1] = v1 + bias[col + 1] + attn[(long long)r * DIM + col + 1] + xres[o1];
                }
            }
        }
    }
}

// ---------------- K4: warp-per-(token,head) QK-norm + RoPE, V copy ----------------
__global__ void qkv_warp(const float* __restrict__ fused,
                         const float* __restrict__ qn_w, const float* __restrict__ qn_b,
                         const float* __restrict__ kn_w, const float* __restrict__ kn_b) {
    int wid  = threadIdx.x >> 5;
    int lane = threadIdx.x & 31;
    int gw = blockIdx.x * 8 + wid;
    int token = gw >> 4;
    int head  = gw & 15;
    int t  = token / HW;
    int hh = (token / RES) % RES;
    int ww = token % RES;

    __shared__ float s_all[8][DH];
    float* s = s_all[wid];

    const float* base = fused + (long long)token * QKVC + head * DH;

    {
        float v0 = base[2 * DIM + lane];
        g_v[((long long)head * THW + token) * DH + lane] = v0;
        if (lane < 16)
            g_v[((long long)head * THW + token) * DH + 32 + lane] = base[2 * DIM + 32 + lane];
    }

    #pragma unroll
    for (int which = 0; which < 2; which++) {
        const float* w  = which ? kn_w : qn_w;
        const float* bb = which ? kn_b : qn_b;
        float v0 = base[which * DIM + lane];
        float v1 = (lane < 16) ? base[which * DIM + 32 + lane] : 0.f;

        float sum = v0 + v1;
        #pragma unroll
        for (int o = 16; o > 0; o >>= 1) sum += __shfl_xor_sync(0xffffffffu, sum, o);
        float mean = sum * (1.f / DH);

        float d0 = v0 - mean;
        float d1 = (lane < 16) ? (v1 - mean) : 0.f;
        float sq = d0 * d0 + d1 * d1;
        #pragma unroll
        for (int o = 16; o > 0; o >>= 1) sq += __shfl_xor_sync(0xffffffffu, sq, o);
        float rstd = rsqrtf(sq * (1.f / DH) + EPS);

        s[lane] = d0 * rstd * w[lane] + bb[lane];
        if (lane < 16)
            s[32 + lane] = d1 * rstd * w[32 + lane] + bb[32 + lane];
        __syncwarp();

        if (lane < DH / 2) {
            int i = lane;
            float x1 = s[2 * i], x2 = s[2 * i + 1];
            float pos = (i < 8) ? (float)t : (i < 16) ? (float)hh : (float)ww;
            int j = i & 7;
            float inv = powf(10000.f, -(float)j * 0.125f);
            float ang = pos * inv;
            float sn, cs;
            sincosf(ang, &sn, &cs);
            float o1 = x1 * cs - x2 * sn;
            float o2 = x1 * sn + x2 * cs;
            float sc = which ? 1.f : 0.14433756729740643f;
            float* dst = (which ? g_k : g_q) + ((long long)head * THW + token) * DH;
            dst[2 * i]     = o1 * sc;
            dst[2 * i + 1] = o2 * sc;
        }
        __syncwarp();
    }
}

// ---------------- K5: tiled neighborhood attention -> fp16 xa ----------------
#define UTOK 432
#define KSTRIDE 50
#define NA_SMEM ((2*UTOK*KSTRIDE + 192*DH + 8*80) * 4 + 8*80*4)

__global__ void __launch_bounds__(256)
nattn_tiled() {
    extern __shared__ float sm[];
    float* Ks = sm;
    float* Vs = Ks + UTOK * KSTRIDE;
    float* Qs = Vs + UTOK * KSTRIDE;
    float* Ps = Qs + 192 * DH;
    int*   Ts = (int*)(Ps + 8 * 80);

    const int tile = blockIdx.x;
    const int head = blockIdx.y;
    const int th0 = (tile / 3) * 8;
    const int tw0 = (tile % 3) * 8;
    const int kh0 = min(max(th0 - 2, 0), RES - 12);
    const int kw0 = min(max(tw0 - 2, 0), RES - 12);
    const int tid  = threadIdx.x;
    const int wid  = tid >> 5;
    const int lane = tid & 31;

    const float* kbase = g_k + (long long)head * THW * DH;
    const float* vbase = g_v + (long long)head * THW * DH;
    const float* qbase = g_q + (long long)head * THW * DH;

    for (int i = tid; i < UTOK * 24; i += 256) {
        int tok = i / 24, u = i % 24;
        int kt = tok / 144, rem = tok % 144;
        int rr = rem / 12, cc = rem % 12;
        int gtok = kt * HW + (kh0 + rr) * RES + (kw0 + cc);
        float2 kv = *(const float2*)(kbase + (long long)gtok * DH + 2 * u);
        float2 vv = *(const float2*)(vbase + (long long)gtok * DH + 2 * u);
        *(float2*)&Ks[tok * KSTRIDE + 2 * u] = kv;
        *(float2*)&Vs[tok * KSTRIDE + 2 * u] = vv;
    }
    for (int i = tid; i < 192 * 24; i += 256) {
        int qi = i / 24, u = i % 24;
        int t = qi / 64, rem = qi % 64;
        int qr = rem / 8, qc = rem % 8;
        int gtok = t * HW + (th0 + qr) * RES + (tw0 + qc);
        *(float2*)&Qs[qi * DH + 2 * u] = *(const float2*)(qbase + (long long)gtok * DH + 2 * u);
    }
    __syncthreads();

    for (int it = 0; it < 24; it++) {
        int qi = wid * 24 + it;
        int t = qi / 64, rem = qi % 64;
        int qr = rem / 8, qc = rem % 8;
        int hq = th0 + qr, wq = tw0 + qc;
        int rb = min(max(hq - 2, 0), RES - KH) - kh0;
        int cb = min(max(wq - 2, 0), RES - KW) - kw0;
        const float* qs = Qs + qi * DH;

        float d[3] = {-1e30f, -1e30f, -1e30f};
        int   tk[3] = {0, 0, 0};
        #pragma unroll
        for (int c = 0; c < 3; c++) {
            int s = lane + 32 * c;
            if (s < NK) {
                int kt = s / 25, r2 = (s % 25) / 5, c2 = s % 5;
                int tok = kt * 144 + (rb + r2) * 12 + (cb + c2);
                tk[c] = tok;
                const float* kp = Ks + tok * KSTRIDE;
                float acc = 0.f;
                #pragma unroll
                for (int u = 0; u < 24; u++) {
                    float2 qv = *(const float2*)(qs + 2 * u);
                    float2 kv = *(const float2*)(kp + 2 * u);
                    acc = fmaf(qv.x, kv.x, acc);
                    acc = fmaf(qv.y, kv.y, acc);
                }
                d[c] = acc;
            }
        }
        float m = fmaxf(d[0], fmaxf(d[1], d[2]));
        #pragma unroll
        for (int o = 16; o > 0; o >>= 1) m = fmaxf(m, __shfl_xor_sync(0xffffffffu, m, o));
        float e[3]; float ssum = 0.f;
        #pragma unroll
        for (int c = 0; c < 3; c++) {
            e[c] = (lane + 32 * c < NK) ? __expf(d[c] - m) : 0.f;
            ssum += e[c];
        }
        #pragma unroll
        for (int o = 16; o > 0; o >>= 1) ssum += __shfl_xor_sync(0xffffffffu, ssum, o);
        float rs = 1.f / ssum;

        #pragma unroll
        for (int c = 0; c < 3; c++) {
            int s = lane + 32 * c;
            if (s < NK) { Ps[wid * 80 + s] = e[c]; Ts[wid * 80 + s] = tk[c]; }
        }
        __syncwarp();

        float o0 = 0.f, o1 = 0.f;
        for (int s = 0; s < NK; s++) {
            float p = Ps[wid * 80 + s];
            int tok = Ts[wid * 80 + s];
            const float* vp = Vs + tok * KSTRIDE;
            o0 = fmaf(p, vp[lane], o0);
            if (lane < 16) o1 = fmaf(p, vp[32 + lane], o1);
        }
        int gtok = t * HW + hq * RES + wq;
        __half* dst = g_xa + (long long)gtok * DIM + head * DH;
        dst[lane] = __float2half_rn(o0 * rs);
        if (lane < 16) dst[32 + lane] = __float2half_rn(o1 * rs);
        __syncwarp();
    }
}

// ---------------- launch ----------------
extern "C" void kernel_launch(void* const* d_in, const int* in_sizes, int n_in,
                              void* d_out, int out_size) {
    const float* x       = (const float*)d_in[0];
    const float* emb     = (const float*)d_in[1];
    const float* w_mod   = (const float*)d_in[2];
    const float* b_mod   = (const float*)d_in[3];
    const float* qn_w    = (const float*)d_in[4];
    const float* qn_b    = (const float*)d_in[5];
    const float* kn_w    = (const float*)d_in[6];
    const float* kn_b    = (const float*)d_in[7];
    const float* W_fused = (const float*)d_in[8];
    const float* b_fused = (const float*)d_in[9];
    const float* W_out   = (const float*)d_in[10];
    const float* W_mlp   = (const float*)d_in[11];
    const float* b_mlp   = (const float*)d_in[12];
    float* out = (float*)d_out;

    __half *p_h, *p_mlpH, *p_xa;
    float *p_qkv, *p_attn;
    uint32_t* p_wH;
    cudaGetSymbolAddress((void**)&p_h,    g_h);
    cudaGetSymbolAddress((void**)&p_qkv,  g_qkv);
    cudaGetSymbolAddress((void**)&p_mlpH, g_mlpH);
    cudaGetSymbolAddress((void**)&p_xa,   g_xa);
    cudaGetSymbolAddress((void**)&p_attn, g_attn);
    cudaGetSymbolAddress((void**)&p_wH,   g_wH);

    cudaFuncSetAttribute(hgemm<2,128>, cudaFuncAttributeMaxDynamicSharedMemorySize, GEMM_SMEM_BM(128));
    cudaFuncSetAttribute(hgemm<0,64>,  cudaFuncAttributeMaxDynamicSharedMemorySize, GEMM_SMEM_BM(64));
    cudaFuncSetAttribute(hgemm<3,64>,  cudaFuncAttributeMaxDynamicSharedMemorySize, GEMM_SMEM_BM(64));
    cudaFuncSetAttribute(nattn_tiled,  cudaFuncAttributeMaxDynamicSharedMemorySize, NA_SMEM);

    // pack all weights to fp16 in one launch
    packAll<<<(WTOT + 255) / 256, 256>>>(W_fused, W_out, W_mlp);

    // mod GEMM: split-K x16 + deterministic reduce
    mod_partial<<<dim3(T_ * 6, KCH), 256>>>(emb, w_mod);
    mod_reduce<<<(T_ * 2 * DIM) / 256, 256>>>(b_mod);

    ln_mod_kernel<<<THW, 256>>>(x);

    // GEMM1: fused; qkv slice fp32 -> g_qkv, mlp slice silu fp16 -> g_mlpH
    hgemm<2,128><<<dim3(NF / 128, 14), 256, GEMM_SMEM_BM(128)>>>(
        p_h, DIM, p_wH + W1OFF, NF, b_fused, p_qkv, QKVC, THW, DIM, nullptr, nullptr);
    qkv_warp<<<(THW * HEADS) / 8, 256>>>(p_qkv, qn_w, qn_b, kn_w, kn_b);
    nattn_tiled<<<dim3(9, HEADS), 256, NA_SMEM>>>();
    // GEMM2: attn = xa @ W_out  (BM=64 -> 162 CTAs, full wave)
    hgemm<0,64><<<dim3(DIM / 128, THW / 64), 256, GEMM_SMEM_BM(64)>>>(
        p_xa, DIM, p_wH + W2OFF, DIM, nullptr, p_attn, DIM, THW, DIM, nullptr, nullptr);
    // GEMM3: out = x + attn + silu(mlp) @ W_mlp + b_mlp  (BM=64 -> 162 CTAs)
    hgemm<3,64><<<dim3(DIM / 128, THW / 64), 256, GEMM_SMEM_BM(64)>>>(
        p_mlpH, MLP, p_wH + W3OFF, DIM, b_mlp, out, DIM, THW, MLP, p_attn, x);
}